// round 12
// baseline (speedup 1.0000x reference)
#include <cuda_runtime.h>
#include <cuda_bf16.h>
#include <cstdint>
#include <math.h>

#define NPTS  50000
#define NVIEW 500000
#define LDS   136   // 128 + 8 bf16 padding -> conflict-free ldmatrix

// ---------------- scratch (device globals; no allocations) ----------------
__device__ int   g_didx[NVIEW];
__device__ float g_q[NPTS * 8];
__device__ float g_ctx[NPTS * 32];
__device__ float g_c2[NPTS * 32];          // ctx @ W2_bottom, per segment
__device__ float g_comp[NVIEW];
__device__ float g_hmod[(size_t)NVIEW * 128];

// ---------------- small utility kernels ----------------
__global__ void k_zero_ctx(int n) {
    int i = blockIdx.x * blockDim.x + threadIdx.x;
    if (i < n) g_ctx[i] = 0.0f;
}
__global__ void k_tail_zero(float* p, int n) {
    int i = blockIdx.x * blockDim.x + threadIdx.x;
    if (i < n) p[i] = 0.0f;
}

// ---------------- per-point queries (x staged in smem) ----------------
__global__ void __launch_bounds__(256) k_q(const float* __restrict__ xm,
                                           const float* __restrict__ W1,
                                           const float* __restrict__ W2,
                                           const float* __restrict__ WQ,
                                           const float* __restrict__ bQ, int N) {
    __shared__ float sW1[64 * 32];
    __shared__ float sW2[32 * 32];
    __shared__ float sWQ[32 * 8];
    __shared__ float sxq[8][64];
    __shared__ float s1[8][32];
    __shared__ float s2[8][32];
    int tid = threadIdx.x;
    for (int i = tid; i < 64 * 32; i += 256) sW1[i] = W1[i];
    for (int i = tid; i < 32 * 32; i += 256) sW2[i] = W2[i];
    for (int i = tid; i < 32 * 8;  i += 256) sWQ[i] = WQ[i];
    __syncthreads();
    int w = tid >> 5, j = tid & 31;
    int p = blockIdx.x * 8 + w;
    if (p >= N) return;
    {
        float2 t = ((const float2*)(xm + (size_t)p * 64))[j];
        sxq[w][j * 2] = t.x; sxq[w][j * 2 + 1] = t.y;
    }
    __syncwarp();
    float acc = 0.f;
#pragma unroll
    for (int i = 0; i < 64; i++) acc += sxq[w][i] * sW1[i * 32 + j];
    s1[w][j] = fmaxf(acc, 0.f);
    __syncwarp();
    acc = 0.f;
#pragma unroll
    for (int i = 0; i < 32; i++) acc += s1[w][i] * sW2[i * 32 + j];
    s2[w][j] = acc;
    __syncwarp();
    if (j < 8) {
        acc = bQ[j];
#pragma unroll
        for (int i = 0; i < 32; i++) acc += s2[w][i] * sWQ[i * 8 + j];
        g_q[p * 8 + j] = acc;
    }
}

// ------ k_h: didx (binary search) + h=relu(x@W1) in regs + aggregated seg-max ------
__global__ void __launch_bounds__(256) k_h(const float* __restrict__ xmap,
                                           const float* __restrict__ W1,
                                           const int* __restrict__ csr,
                                           int N, int V) {
    __shared__ float sW[16 * 32];
    __shared__ float sx[8][68];     // 4 views x 16 floats (+pad)
    int tid = threadIdx.x;
    for (int i = tid; i < 16 * 32; i += 256) sW[i] = W1[i];
    __syncthreads();
    int w = tid >> 5, j = tid & 31;
    int v0 = (blockIdx.x * 8 + w) * 4;
    if (v0 >= V) return;
    int nv = V - v0; if (nv > 4) nv = 4;

    // lanes 0..3: binary search didx for view v0+j, write it out
    int myseg = 0;
    if (j < 4 && j < nv) {
        int v = v0 + j;
        int lo = 0, hi = N - 1;
        while (lo < hi) {
            int mid = (lo + hi) >> 1;
            if (csr[mid + 1] <= v) lo = mid + 1; else hi = mid;
        }
        myseg = lo;
        g_didx[v] = lo;
    }
    int seg[4];
#pragma unroll
    for (int u = 0; u < 4; u++) seg[u] = __shfl_sync(0xffffffff, myseg, u, 32);

    if (v0 + 3 < V) {
        if (j < 16) {
            float4 t = ((const float4*)xmap)[(size_t)v0 * 4 + j];
            float* d = &sx[w][j * 4];
            d[0] = t.x; d[1] = t.y; d[2] = t.z; d[3] = t.w;
        }
    } else {
        for (int idx = j; idx < nv * 16; idx += 32)
            sx[w][idx] = xmap[(size_t)v0 * 16 + idx];
    }
    __syncwarp();

    float h[4];
#pragma unroll
    for (int u = 0; u < 4; u++) {
        if (u < nv) {
            float acc = 0.f;
#pragma unroll
            for (int i = 0; i < 16; i++) acc += sx[w][u * 16 + i] * sW[i * 32 + j];
            h[u] = fmaxf(acc, 0.f);
        }
    }
    // aggregate consecutive same-segment maxes before atomics (relu>=0, int cmp ok)
    float m = h[0]; int cs = seg[0];
#pragma unroll
    for (int u = 1; u < 4; u++) {
        if (u < nv) {
            if (seg[u] == cs) m = fmaxf(m, h[u]);
            else {
                atomicMax((int*)&g_ctx[cs * 32 + j], __float_as_int(m));
                cs = seg[u]; m = h[u];
            }
        }
    }
    atomicMax((int*)&g_ctx[cs * 32 + j], __float_as_int(m));
}

// -------- per-segment: c2 = ctx @ W2[32:64] (the ctx half of the concat matvec) --------
__global__ void __launch_bounds__(256) k_ctx2(const float* __restrict__ W2, int N) {
    __shared__ float sW[32 * 32];
    __shared__ float sx[8][32];
    int tid = threadIdx.x;
    for (int i = tid; i < 32 * 32; i += 256) sW[i] = W2[32 * 32 + i];  // rows 32..63
    __syncthreads();
    int w = tid >> 5, j = tid & 31;
    int p = blockIdx.x * 8 + w;
    if (p >= N) return;
    sx[w][j] = g_ctx[p * 32 + j];
    __syncwarp();
    float acc = 0.f;
#pragma unroll
    for (int i = 0; i < 32; i++) acc += sx[w][i] * sW[i * 32 + j];
    g_c2[p * 32 + j] = acc;
}

// ------- per-view comp (4 views/warp; h recomputed from x_map, bit-identical) -------
__global__ void __launch_bounds__(256) k_comp(const float* __restrict__ xmap,
                                              const float* __restrict__ W1,
                                              const float* __restrict__ W2,
                                              const float* __restrict__ WK,
                                              const float* __restrict__ bK, int V) {
    __shared__ float sW1[16 * 32];
    __shared__ float sW[32 * 32];
    __shared__ float sWK[32 * 8];
    __shared__ float sx[8][68];
    __shared__ float cat[8][132];
    __shared__ float kv[8][132];
    int tid = threadIdx.x;
    for (int i = tid; i < 16 * 32; i += 256) sW1[i] = W1[i];
    for (int i = tid; i < 32 * 32; i += 256) sW[i] = W2[i];          // rows 0..31 (h part)
    for (int i = tid; i < 32 * 8;  i += 256) sWK[i] = WK[i];
    __syncthreads();
    int w = tid >> 5, j = tid & 31;
    int v0 = (blockIdx.x * 8 + w) * 4;
    if (v0 >= V) return;
    int nv = V - v0; if (nv > 4) nv = 4;

    if (v0 + 3 < V) {
        if (j < 16) {
            float4 t = ((const float4*)xmap)[(size_t)v0 * 4 + j];
            float* d = &sx[w][j * 4];
            d[0] = t.x; d[1] = t.y; d[2] = t.z; d[3] = t.w;
        }
    } else {
        for (int idx = j; idx < nv * 16; idx += 32)
            sx[w][idx] = xmap[(size_t)v0 * 16 + idx];
    }
    __syncwarp();

    // recompute h (same FMA order as k_h -> bit-identical), park in cat
#pragma unroll
    for (int u = 0; u < 4; u++) {
        if (u < nv) {
            float acc = 0.f;
#pragma unroll
            for (int i = 0; i < 16; i++) acc += sx[w][u * 16 + i] * sW1[i * 32 + j];
            cat[w][u * 32 + j] = fmaxf(acc, 0.f);
        }
    }
    __syncwarp();

    int seg[4];
#pragma unroll
    for (int u = 0; u < 4; u++) {
        if (u < nv) {
            seg[u] = g_didx[v0 + u];
            float acc = g_c2[seg[u] * 32 + j];
#pragma unroll
            for (int i = 0; i < 32; i++) acc += cat[w][u * 32 + i] * sW[i * 32 + j];
            kv[w][u * 32 + j] = fmaxf(acc, 0.f);
        }
    }
    __syncwarp();

    // lane groups of 8: group u computes keys for view u
    int u = j >> 3, jq = j & 7;
    float c = 0.f;
    if (u < nv) {
        int segu = g_didx[v0 + u];
        float key = bK[jq];
#pragma unroll
        for (int i = 0; i < 32; i++) key += kv[w][u * 32 + i] * sWK[i * 8 + jq];
        c = key * g_q[segu * 8 + jq];
    }
    c += __shfl_down_sync(0xffffffff, c, 4, 8);
    c += __shfl_down_sync(0xffffffff, c, 2, 8);
    c += __shfl_down_sync(0xffffffff, c, 1, 8);
    if (jq == 0 && u < nv) g_comp[v0 + u] = c * 0.35355339059327373f;
}

// ---------------- tensor-core fused 2-layer GEMM (split-bf16, 3-MMA, M=256) ----------------
__device__ __forceinline__ uint32_t sm_addr(const void* p) {
    return (uint32_t)__cvta_generic_to_shared(p);
}
__device__ __forceinline__ void ldsm4(uint32_t a, uint32_t* r) {
    asm volatile("ldmatrix.sync.aligned.m8n8.x4.shared.b16 {%0,%1,%2,%3}, [%4];"
                 : "=r"(r[0]), "=r"(r[1]), "=r"(r[2]), "=r"(r[3]) : "r"(a));
}
__device__ __forceinline__ void ldsm4t(uint32_t a, uint32_t* r) {
    asm volatile("ldmatrix.sync.aligned.m8n8.x4.trans.shared.b16 {%0,%1,%2,%3}, [%4];"
                 : "=r"(r[0]), "=r"(r[1]), "=r"(r[2]), "=r"(r[3]) : "r"(a));
}
__device__ __forceinline__ void mma16816(float* d, const uint32_t* a, uint32_t b0, uint32_t b1) {
    asm volatile("mma.sync.aligned.m16n8k16.row.col.f32.bf16.bf16.f32 "
                 "{%0,%1,%2,%3}, {%4,%5,%6,%7}, {%8,%9}, {%0,%1,%2,%3};"
                 : "+f"(d[0]), "+f"(d[1]), "+f"(d[2]), "+f"(d[3])
                 : "r"(a[0]), "r"(a[1]), "r"(a[2]), "r"(a[3]), "r"(b0), "r"(b1));
}
__device__ __forceinline__ void split4(float4 v, __nv_bfloat16* hi, __nv_bfloat16* lo) {
    float f[4] = {v.x, v.y, v.z, v.w};
    __nv_bfloat162 h01, h23, l01, l23;
    __nv_bfloat16 h0 = __float2bfloat16_rn(f[0]);
    __nv_bfloat16 h1 = __float2bfloat16_rn(f[1]);
    __nv_bfloat16 h2 = __float2bfloat16_rn(f[2]);
    __nv_bfloat16 h3 = __float2bfloat16_rn(f[3]);
    h01.x = h0; h01.y = h1; h23.x = h2; h23.y = h3;
    l01.x = __float2bfloat16_rn(f[0] - __bfloat162float(h0));
    l01.y = __float2bfloat16_rn(f[1] - __bfloat162float(h1));
    l23.x = __float2bfloat16_rn(f[2] - __bfloat162float(h2));
    l23.y = __float2bfloat16_rn(f[3] - __bfloat162float(h3));
    *reinterpret_cast<__nv_bfloat162*>(hi)     = h01;
    *reinterpret_cast<__nv_bfloat162*>(hi + 2) = h23;
    *reinterpret_cast<__nv_bfloat162*>(lo)     = l01;
    *reinterpret_cast<__nv_bfloat162*>(lo + 2) = l23;
}

// acc layout: acc[c][t][4]; A and B fragments double-buffered; ks fully unrolled.
__device__ __forceinline__ void gemm_loop(uint32_t aHi0, uint32_t aLo0,
                                          uint32_t bHi, uint32_t bLo,
                                          float (&acc)[2][16][4]) {
    const uint32_t CH = 16 * LDS * 2;
    uint32_t ah[2][2][4], al[2][2][4];
    ldsm4(aHi0,      ah[0][0]);
    ldsm4(aLo0,      al[0][0]);
    ldsm4(aHi0 + CH, ah[0][1]);
    ldsm4(aLo0 + CH, al[0][1]);
#pragma unroll
    for (int ks = 0; ks < 8; ks++) {
        const int cab = ks & 1, nab = cab ^ 1;
        if (ks < 7) {
            ldsm4(aHi0 + (ks + 1) * 32,      ah[nab][0]);
            ldsm4(aLo0 + (ks + 1) * 32,      al[nab][0]);
            ldsm4(aHi0 + CH + (ks + 1) * 32, ah[nab][1]);
            ldsm4(aLo0 + CH + (ks + 1) * 32, al[nab][1]);
        }
        uint32_t bBaseH = bHi + (uint32_t)(ks * 16 * LDS) * 2u;
        uint32_t bBaseL = bLo + (uint32_t)(ks * 16 * LDS) * 2u;
        uint32_t bh[2][4], bl[2][4];
        ldsm4t(bBaseH, bh[0]);
        ldsm4t(bBaseL, bl[0]);
#pragma unroll
        for (int np = 0; np < 8; np++) {
            const int cur = np & 1, nxt = cur ^ 1;
            if (np < 7) {
                ldsm4t(bBaseH + (np + 1) * 32, bh[nxt]);
                ldsm4t(bBaseL + (np + 1) * 32, bl[nxt]);
            }
#pragma unroll
            for (int c = 0; c < 2; c++) {
                mma16816(acc[c][np * 2],     ah[cab][c], bh[cur][0], bh[cur][1]);
                mma16816(acc[c][np * 2 + 1], ah[cab][c], bh[cur][2], bh[cur][3]);
                mma16816(acc[c][np * 2],     ah[cab][c], bl[cur][0], bl[cur][1]);
                mma16816(acc[c][np * 2 + 1], ah[cab][c], bl[cur][2], bl[cur][3]);
                mma16816(acc[c][np * 2],     al[cab][c], bh[cur][0], bh[cur][1]);
                mma16816(acc[c][np * 2 + 1], al[cab][c], bh[cur][2], bh[cur][3]);
            }
        }
    }
}

#define MT 256                              // M tile
#define FUSED_SMEM ((2 * MT + 2 * 128) * LDS * 2)

// out[M,128] = relu(X[M,128] @ W1) @ W2
__global__ void __launch_bounds__(256, 1) k_fused_mod(const float* __restrict__ X,
                                                      const float* __restrict__ W1,
                                                      const float* __restrict__ W2,
                                                      float* __restrict__ out, int M) {
    extern __shared__ __nv_bfloat16 sm[];
    __nv_bfloat16* sAhi = sm;
    __nv_bfloat16* sAlo = sm + (size_t)MT * LDS;
    __nv_bfloat16* sBhi = sm + (size_t)2 * MT * LDS;
    __nv_bfloat16* sBlo = sBhi + (size_t)128 * LDS;

    int tid = threadIdx.x;
    int m0 = blockIdx.x * MT;

    for (int idx = tid; idx < MT * 32; idx += 256) {
        int r = idx >> 5, c4 = idx & 31;
        float4 v = (m0 + r < M) ? ((const float4*)X)[(size_t)(m0 + r) * 32 + c4]
                                : make_float4(0.f, 0.f, 0.f, 0.f);
        split4(v, sAhi + r * LDS + c4 * 4, sAlo + r * LDS + c4 * 4);
    }
    for (int idx = tid; idx < 128 * 32; idx += 256) {
        int r = idx >> 5, c4 = idx & 31;
        float4 v = ((const float4*)W1)[idx];
        split4(v, sBhi + r * LDS + c4 * 4, sBlo + r * LDS + c4 * 4);
    }
    __syncthreads();

    int w = tid >> 5, lane = tid & 31;
    int lr = lane & 15, lc = (lane >> 4) * 8;
    uint32_t aHi = sm_addr(sAhi + (w * 32 + lr) * LDS + lc);
    uint32_t aLo = sm_addr(sAlo + (w * 32 + lr) * LDS + lc);
    uint32_t bHi = sm_addr(sBhi + lr * LDS + lc);
    uint32_t bLo = sm_addr(sBlo + lr * LDS + lc);

    float acc[2][16][4];
#pragma unroll
    for (int c = 0; c < 2; c++)
#pragma unroll
        for (int t = 0; t < 16; t++)
#pragma unroll
            for (int i = 0; i < 4; i++) acc[c][t][i] = 0.f;

    // ---- layer 1 ----
    gemm_loop(aHi, aLo, bHi, bLo, acc);

    int grp = lane >> 2, tq = lane & 3;
#pragma unroll
    for (int c = 0; c < 2; c++)
#pragma unroll
    for (int t = 0; t < 16; t++) {
        int col = t * 8 + tq * 2;
        int r0 = w * 32 + c * 16 + grp, r1 = r0 + 8;
        float v0 = fmaxf(acc[c][t][0], 0.f), v1 = fmaxf(acc[c][t][1], 0.f);
        float v2 = fmaxf(acc[c][t][2], 0.f), v3 = fmaxf(acc[c][t][3], 0.f);
        __nv_bfloat16 h0 = __float2bfloat16_rn(v0), h1 = __float2bfloat16_rn(v1);
        __nv_bfloat16 h2 = __float2bfloat16_rn(v2), h3 = __float2bfloat16_rn(v3);
        __nv_bfloat162 p;
        p.x = h0; p.y = h1;
        *reinterpret_cast<__nv_bfloat162*>(&sAhi[r0 * LDS + col]) = p;
        p.x = h2; p.y = h3;
        *reinterpret_cast<__nv_bfloat162*>(&sAhi[r1 * LDS + col]) = p;
        p.x = __float2bfloat16_rn(v0 - __bfloat162float(h0));
        p.y = __float2bfloat16_rn(v1 - __bfloat162float(h1));
        *reinterpret_cast<__nv_bfloat162*>(&sAlo[r0 * LDS + col]) = p;
        p.x = __float2bfloat16_rn(v2 - __bfloat162float(h2));
        p.y = __float2bfloat16_rn(v3 - __bfloat162float(h3));
        *reinterpret_cast<__nv_bfloat162*>(&sAlo[r1 * LDS + col]) = p;
    }
    __syncthreads();

    for (int idx = tid; idx < 128 * 32; idx += 256) {
        int r = idx >> 5, c4 = idx & 31;
        float4 v = ((const float4*)W2)[idx];
        split4(v, sBhi + r * LDS + c4 * 4, sBlo + r * LDS + c4 * 4);
    }
    __syncthreads();

#pragma unroll
    for (int c = 0; c < 2; c++)
#pragma unroll
        for (int t = 0; t < 16; t++)
#pragma unroll
            for (int i = 0; i < 4; i++) acc[c][t][i] = 0.f;

    // ---- layer 2 ----
    gemm_loop(aHi, aLo, bHi, bLo, acc);

#pragma unroll
    for (int c = 0; c < 2; c++)
#pragma unroll
    for (int t = 0; t < 16; t++) {
        int col = t * 8 + tq * 2;
        int gm0 = m0 + w * 32 + c * 16 + grp;
        int gm1 = gm0 + 8;
        if (gm0 < M) {
            float2 o; o.x = acc[c][t][0]; o.y = acc[c][t][1];
            *reinterpret_cast<float2*>(&out[(size_t)gm0 * 128 + col]) = o;
        }
        if (gm1 < M) {
            float2 o; o.x = acc[c][t][2]; o.y = acc[c][t][3];
            *reinterpret_cast<float2*>(&out[(size_t)gm1 * 128 + col]) = o;
        }
    }
}

// ---------------- per-segment softmax + pooling + gate ----------------
__global__ void __launch_bounds__(128) k_pool(const int* __restrict__ csr,
                                              const float* __restrict__ gw,
                                              const float* __restrict__ gb,
                                              float* __restrict__ out,
                                              float* __restrict__ seen,
                                              int writeSeen) {
    int n = blockIdx.x;
    int s = csr[n], e = csr[n + 1];
    int tid = threadIdx.x;
    __shared__ float red[128];
    if (e <= s) {
        out[(size_t)n * 128 + tid] = 0.f;
        if (writeSeen && tid == 0) seen[n] = 0.f;
        return;
    }
    float m = -INFINITY;
    for (int v = s + tid; v < e; v += 128) m = fmaxf(m, g_comp[v]);
    red[tid] = m; __syncthreads();
#pragma unroll
    for (int off = 64; off > 0; off >>= 1) {
        if (tid < off) red[tid] = fmaxf(red[tid], red[tid + off]);
        __syncthreads();
    }
    m = red[0];
    __syncthreads();
    float sum = 0.f;
    for (int v = s + tid; v < e; v += 128) sum += expf(g_comp[v] - m);
    red[tid] = sum; __syncthreads();
#pragma unroll
    for (int off = 64; off > 0; off >>= 1) {
        if (tid < off) red[tid] += red[tid + off];
        __syncthreads();
    }
    float inv = 1.f / (red[0] + 1e-12f);
    float acc = 0.f;
    for (int v = s; v < e; v++) {
        float wgt = expf(g_comp[v] - m) * inv;
        acc += wgt * g_hmod[(size_t)v * 128 + tid];
    }
    float gi = gw[0] * m + gb[0];
    float gate = tanhf(fmaxf(gi, 0.f));
    out[(size_t)n * 128 + tid] = acc * gate;
    if (writeSeen && tid == 0) seen[n] = 1.f;
}

// ---------------- launch ----------------
extern "C" void kernel_launch(void* const* d_in, const int* in_sizes, int n_in,
                              void* d_out, int out_size) {
    const float* x_main  = (const float*)d_in[0];
    const float* x_mod   = (const float*)d_in[1];
    const float* x_map   = (const float*)d_in[2];
    const int*   csr     = (const int*)  d_in[3];
    const float* W_main1 = (const float*)d_in[4];
    const float* W_main2 = (const float*)d_in[5];
    const float* W_map1  = (const float*)d_in[6];
    const float* W_map2  = (const float*)d_in[7];
    const float* W_mod1  = (const float*)d_in[8];
    const float* W_mod2  = (const float*)d_in[9];
    const float* WQ      = (const float*)d_in[10];
    const float* bQ      = (const float*)d_in[11];
    const float* WK      = (const float*)d_in[12];
    const float* bK      = (const float*)d_in[13];
    const float* gw      = (const float*)d_in[14];
    const float* gb      = (const float*)d_in[15];

    int N = in_sizes[3] - 1;
    int V = in_sizes[2] / 16;

    float* out = (float*)d_out;
    float* seen = nullptr;
    int writeSeen = 0;
    long long written = (long long)N * 128;
    if ((long long)out_size >= (long long)N * 128 + N) {
        seen = out + (size_t)N * 128;
        writeSeen = 1;
        written += N;
    }

    void* hmodPtr = nullptr;
    cudaGetSymbolAddress(&hmodPtr, g_hmod);
    float* hmod = (float*)hmodPtr;

    k_zero_ctx<<<(N * 32 + 255) / 256, 256>>>(N * 32);
    k_q<<<(N + 7) / 8, 256>>>(x_main, W_main1, W_main2, WQ, bQ, N);
    k_h<<<(V + 31) / 32, 256>>>(x_map, W_map1, csr, N, V);
    k_ctx2<<<(N + 7) / 8, 256>>>(W_map2, N);
    k_comp<<<(V + 31) / 32, 256>>>(x_map, W_map1, W_map2, WK, bK, V);

    cudaFuncSetAttribute(k_fused_mod, cudaFuncAttributeMaxDynamicSharedMemorySize, FUSED_SMEM);
    k_fused_mod<<<(V + MT - 1) / MT, 256, FUSED_SMEM>>>(x_mod, W_mod1, W_mod2, hmod, V);

    k_pool<<<N, 128>>>(csr, gw, gb, out, seen, writeSeen);

    long long tail = (long long)out_size - written;
    if (tail > 0) {
        k_tail_zero<<<(int)((tail + 255) / 256), 256>>>(out + written, (int)tail);
    }
}

// round 13
// speedup vs baseline: 1.0803x; 1.0803x over previous
#include <cuda_runtime.h>
#include <cuda_bf16.h>
#include <cstdint>
#include <math.h>

#define NPTS  50000
#define NVIEW 500000
#define LDS   136   // 128 + 8 bf16 padding -> conflict-free ldmatrix

// ---------------- scratch (device globals; no allocations) ----------------
__device__ int   g_didx[NVIEW];
__device__ float g_q[NPTS * 8];
__device__ float g_h[(size_t)NVIEW * 32];
__device__ float g_ctx[NPTS * 32];
__device__ float g_c2[NPTS * 32];          // ctx @ W2_bottom, per segment
__device__ float g_comp[NVIEW];
__device__ float g_hmod[(size_t)NVIEW * 128];

// ---------------- small utility kernels ----------------
__global__ void k_zero_ctx(int n) {
    int i = blockIdx.x * blockDim.x + threadIdx.x;
    if (i < n) g_ctx[i] = 0.0f;
}
__global__ void k_tail_zero(float* p, int n) {
    int i = blockIdx.x * blockDim.x + threadIdx.x;
    if (i < n) p[i] = 0.0f;
}

__global__ void k_didx(const int* __restrict__ csr, int N, int V) {
    int v = blockIdx.x * blockDim.x + threadIdx.x;
    if (v >= V) return;
    int lo = 0, hi = N - 1;
    while (lo < hi) {
        int mid = (lo + hi) >> 1;
        if (csr[mid + 1] <= v) lo = mid + 1; else hi = mid;
    }
    g_didx[v] = lo;
}

// ---------------- per-point queries (x staged in smem) ----------------
__global__ void __launch_bounds__(256) k_q(const float* __restrict__ xm,
                                           const float* __restrict__ W1,
                                           const float* __restrict__ W2,
                                           const float* __restrict__ WQ,
                                           const float* __restrict__ bQ, int N) {
    __shared__ float sW1[64 * 32];
    __shared__ float sW2[32 * 32];
    __shared__ float sWQ[32 * 8];
    __shared__ float sxq[8][64];
    __shared__ float s1[8][32];
    __shared__ float s2[8][32];
    int tid = threadIdx.x;
    for (int i = tid; i < 64 * 32; i += 256) sW1[i] = W1[i];
    for (int i = tid; i < 32 * 32; i += 256) sW2[i] = W2[i];
    for (int i = tid; i < 32 * 8;  i += 256) sWQ[i] = WQ[i];
    __syncthreads();
    int w = tid >> 5, j = tid & 31;
    int p = blockIdx.x * 8 + w;
    if (p >= N) return;
    {
        float2 t = ((const float2*)(xm + (size_t)p * 64))[j];
        sxq[w][j * 2] = t.x; sxq[w][j * 2 + 1] = t.y;
    }
    __syncwarp();
    float acc = 0.f;
#pragma unroll
    for (int i = 0; i < 64; i++) acc += sxq[w][i] * sW1[i * 32 + j];
    s1[w][j] = fmaxf(acc, 0.f);
    __syncwarp();
    acc = 0.f;
#pragma unroll
    for (int i = 0; i < 32; i++) acc += s1[w][i] * sW2[i * 32 + j];
    s2[w][j] = acc;
    __syncwarp();
    if (j < 8) {
        acc = bQ[j];
#pragma unroll
        for (int i = 0; i < 32; i++) acc += s2[w][i] * sWQ[i * 8 + j];
        g_q[p * 8 + j] = acc;
    }
}

// ------ per-view h = relu(x_map@W_map1); 4 views/warp, aggregated seg-max ------
__global__ void __launch_bounds__(256) k_h(const float* __restrict__ xmap,
                                           const float* __restrict__ W1, int V) {
    __shared__ float sW[16 * 32];
    __shared__ float sx[8][68];     // 4 views x 16 floats (+pad)
    int tid = threadIdx.x;
    for (int i = tid; i < 16 * 32; i += 256) sW[i] = W1[i];
    __syncthreads();
    int w = tid >> 5, j = tid & 31;
    int v0 = (blockIdx.x * 8 + w) * 4;
    if (v0 >= V) return;
    int nv = V - v0; if (nv > 4) nv = 4;

    if (v0 + 3 < V) {
        if (j < 16) {
            float4 t = ((const float4*)xmap)[(size_t)v0 * 4 + j];
            float* d = &sx[w][j * 4];
            d[0] = t.x; d[1] = t.y; d[2] = t.z; d[3] = t.w;
        }
    } else {
        for (int idx = j; idx < nv * 16; idx += 32)
            sx[w][idx] = xmap[(size_t)v0 * 16 + idx];
    }
    __syncwarp();

    float h[4];
    int seg[4];
#pragma unroll
    for (int u = 0; u < 4; u++) {
        if (u < nv) {
            float acc = 0.f;
#pragma unroll
            for (int i = 0; i < 16; i++) acc += sx[w][u * 16 + i] * sW[i * 32 + j];
            h[u] = fmaxf(acc, 0.f);
            g_h[(size_t)(v0 + u) * 32 + j] = h[u];
            seg[u] = g_didx[v0 + u];
        }
    }
    // aggregate consecutive same-segment maxes before atomics (relu>=0, int cmp ok)
    float m = h[0]; int cs = seg[0];
#pragma unroll
    for (int u = 1; u < 4; u++) {
        if (u < nv) {
            if (seg[u] == cs) m = fmaxf(m, h[u]);
            else {
                atomicMax((int*)&g_ctx[cs * 32 + j], __float_as_int(m));
                cs = seg[u]; m = h[u];
            }
        }
    }
    atomicMax((int*)&g_ctx[cs * 32 + j], __float_as_int(m));
}

// -------- per-segment: c2 = ctx @ W2[32:64] (the ctx half of the concat matvec) --------
__global__ void __launch_bounds__(256) k_ctx2(const float* __restrict__ W2, int N) {
    __shared__ float sW[32 * 32];
    __shared__ float sx[8][32];
    int tid = threadIdx.x;
    for (int i = tid; i < 32 * 32; i += 256) sW[i] = W2[32 * 32 + i];  // rows 32..63
    __syncthreads();
    int w = tid >> 5, j = tid & 31;
    int p = blockIdx.x * 8 + w;
    if (p >= N) return;
    sx[w][j] = g_ctx[p * 32 + j];
    __syncwarp();
    float acc = 0.f;
#pragma unroll
    for (int i = 0; i < 32; i++) acc += sx[w][i] * sW[i * 32 + j];
    g_c2[p * 32 + j] = acc;
}

// ---------------- per-view comp (4 views/warp, parallel key groups) ----------------
__global__ void __launch_bounds__(256) k_comp(const float* __restrict__ W2,
                                              const float* __restrict__ WK,
                                              const float* __restrict__ bK, int V) {
    __shared__ float sW[32 * 32];
    __shared__ float sWK[32 * 8];
    __shared__ float cat[8][132];
    __shared__ float kv[8][132];
    int tid = threadIdx.x;
    for (int i = tid; i < 32 * 32; i += 256) sW[i] = W2[i];          // rows 0..31 (h part)
    for (int i = tid; i < 32 * 8;  i += 256) sWK[i] = WK[i];
    __syncthreads();
    int w = tid >> 5, j = tid & 31;
    int v0 = (blockIdx.x * 8 + w) * 4;
    if (v0 >= V) return;
    int nv = V - v0; if (nv > 4) nv = 4;

    if (v0 + 3 < V) {
        float4 t = ((const float4*)(g_h + (size_t)v0 * 32))[j];
        float* d = &cat[w][j * 4];
        d[0] = t.x; d[1] = t.y; d[2] = t.z; d[3] = t.w;
    } else {
        for (int idx = j; idx < nv * 32; idx += 32)
            cat[w][idx] = g_h[(size_t)v0 * 32 + idx];
    }
    __syncwarp();

    int seg[4];
#pragma unroll
    for (int u = 0; u < 4; u++) {
        if (u < nv) {
            seg[u] = g_didx[v0 + u];
            float acc = g_c2[seg[u] * 32 + j];
#pragma unroll
            for (int i = 0; i < 32; i++) acc += cat[w][u * 32 + i] * sW[i * 32 + j];
            kv[w][u * 32 + j] = fmaxf(acc, 0.f);
        }
    }
    __syncwarp();

    // lane groups of 8: group u computes keys for view u
    int u = j >> 3, jq = j & 7;
    float c = 0.f;
    if (u < nv) {
        int segu = g_didx[v0 + u];
        float key = bK[jq];
#pragma unroll
        for (int i = 0; i < 32; i++) key += kv[w][u * 32 + i] * sWK[i * 8 + jq];
        c = key * g_q[segu * 8 + jq];
    }
    c += __shfl_down_sync(0xffffffff, c, 4, 8);
    c += __shfl_down_sync(0xffffffff, c, 2, 8);
    c += __shfl_down_sync(0xffffffff, c, 1, 8);
    if (jq == 0 && u < nv) g_comp[v0 + u] = c * 0.35355339059327373f;
}

// ---------------- tensor-core fused 2-layer GEMM (split-bf16, 3-MMA, M=256) ----------------
__device__ __forceinline__ uint32_t sm_addr(const void* p) {
    return (uint32_t)__cvta_generic_to_shared(p);
}
__device__ __forceinline__ void ldsm4(uint32_t a, uint32_t* r) {
    asm volatile("ldmatrix.sync.aligned.m8n8.x4.shared.b16 {%0,%1,%2,%3}, [%4];"
                 : "=r"(r[0]), "=r"(r[1]), "=r"(r[2]), "=r"(r[3]) : "r"(a));
}
__device__ __forceinline__ void ldsm4t(uint32_t a, uint32_t* r) {
    asm volatile("ldmatrix.sync.aligned.m8n8.x4.trans.shared.b16 {%0,%1,%2,%3}, [%4];"
                 : "=r"(r[0]), "=r"(r[1]), "=r"(r[2]), "=r"(r[3]) : "r"(a));
}
__device__ __forceinline__ void mma16816(float* d, const uint32_t* a, uint32_t b0, uint32_t b1) {
    asm volatile("mma.sync.aligned.m16n8k16.row.col.f32.bf16.bf16.f32 "
                 "{%0,%1,%2,%3}, {%4,%5,%6,%7}, {%8,%9}, {%0,%1,%2,%3};"
                 : "+f"(d[0]), "+f"(d[1]), "+f"(d[2]), "+f"(d[3])
                 : "r"(a[0]), "r"(a[1]), "r"(a[2]), "r"(a[3]), "r"(b0), "r"(b1));
}
__device__ __forceinline__ void split4(float4 v, __nv_bfloat16* hi, __nv_bfloat16* lo) {
    float f[4] = {v.x, v.y, v.z, v.w};
    __nv_bfloat162 h01, h23, l01, l23;
    __nv_bfloat16 h0 = __float2bfloat16_rn(f[0]);
    __nv_bfloat16 h1 = __float2bfloat16_rn(f[1]);
    __nv_bfloat16 h2 = __float2bfloat16_rn(f[2]);
    __nv_bfloat16 h3 = __float2bfloat16_rn(f[3]);
    h01.x = h0; h01.y = h1; h23.x = h2; h23.y = h3;
    l01.x = __float2bfloat16_rn(f[0] - __bfloat162float(h0));
    l01.y = __float2bfloat16_rn(f[1] - __bfloat162float(h1));
    l23.x = __float2bfloat16_rn(f[2] - __bfloat162float(h2));
    l23.y = __float2bfloat16_rn(f[3] - __bfloat162float(h3));
    *reinterpret_cast<__nv_bfloat162*>(hi)     = h01;
    *reinterpret_cast<__nv_bfloat162*>(hi + 2) = h23;
    *reinterpret_cast<__nv_bfloat162*>(lo)     = l01;
    *reinterpret_cast<__nv_bfloat162*>(lo + 2) = l23;
}

// acc layout: acc[c][t][4]; A and B fragments double-buffered; ks fully unrolled.
__device__ __forceinline__ void gemm_loop(uint32_t aHi0, uint32_t aLo0,
                                          uint32_t bHi, uint32_t bLo,
                                          float (&acc)[2][16][4]) {
    const uint32_t CH = 16 * LDS * 2;
    uint32_t ah[2][2][4], al[2][2][4];
    ldsm4(aHi0,      ah[0][0]);
    ldsm4(aLo0,      al[0][0]);
    ldsm4(aHi0 + CH, ah[0][1]);
    ldsm4(aLo0 + CH, al[0][1]);
#pragma unroll
    for (int ks = 0; ks < 8; ks++) {
        const int cab = ks & 1, nab = cab ^ 1;
        if (ks < 7) {
            ldsm4(aHi0 + (ks + 1) * 32,      ah[nab][0]);
            ldsm4(aLo0 + (ks + 1) * 32,      al[nab][0]);
            ldsm4(aHi0 + CH + (ks + 1) * 32, ah[nab][1]);
            ldsm4(aLo0 + CH + (ks + 1) * 32, al[nab][1]);
        }
        uint32_t bBaseH = bHi + (uint32_t)(ks * 16 * LDS) * 2u;
        uint32_t bBaseL = bLo + (uint32_t)(ks * 16 * LDS) * 2u;
        uint32_t bh[2][4], bl[2][4];
        ldsm4t(bBaseH, bh[0]);
        ldsm4t(bBaseL, bl[0]);
#pragma unroll
        for (int np = 0; np < 8; np++) {
            const int cur = np & 1, nxt = cur ^ 1;
            if (np < 7) {
                ldsm4t(bBaseH + (np + 1) * 32, bh[nxt]);
                ldsm4t(bBaseL + (np + 1) * 32, bl[nxt]);
            }
#pragma unroll
            for (int c = 0; c < 2; c++) {
                mma16816(acc[c][np * 2],     ah[cab][c], bh[cur][0], bh[cur][1]);
                mma16816(acc[c][np * 2 + 1], ah[cab][c], bh[cur][2], bh[cur][3]);
                mma16816(acc[c][np * 2],     ah[cab][c], bl[cur][0], bl[cur][1]);
                mma16816(acc[c][np * 2 + 1], ah[cab][c], bl[cur][2], bl[cur][3]);
                mma16816(acc[c][np * 2],     al[cab][c], bh[cur][0], bh[cur][1]);
                mma16816(acc[c][np * 2 + 1], al[cab][c], bh[cur][2], bh[cur][3]);
            }
        }
    }
}

#define MT 256                              // M tile
#define FUSED_SMEM ((2 * MT + 2 * 128) * LDS * 2)

// out[M,128] = relu(X[M,128] @ W1) @ W2
__global__ void __launch_bounds__(256, 1) k_fused_mod(const float* __restrict__ X,
                                                      const float* __restrict__ W1,
                                                      const float* __restrict__ W2,
                                                      float* __restrict__ out, int M) {
    extern __shared__ __nv_bfloat16 sm[];
    __nv_bfloat16* sAhi = sm;
    __nv_bfloat16* sAlo = sm + (size_t)MT * LDS;
    __nv_bfloat16* sBhi = sm + (size_t)2 * MT * LDS;
    __nv_bfloat16* sBlo = sBhi + (size_t)128 * LDS;

    int tid = threadIdx.x;
    int m0 = blockIdx.x * MT;

    for (int idx = tid; idx < MT * 32; idx += 256) {
        int r = idx >> 5, c4 = idx & 31;
        float4 v = (m0 + r < M) ? ((const float4*)X)[(size_t)(m0 + r) * 32 + c4]
                                : make_float4(0.f, 0.f, 0.f, 0.f);
        split4(v, sAhi + r * LDS + c4 * 4, sAlo + r * LDS + c4 * 4);
    }
    for (int idx = tid; idx < 128 * 32; idx += 256) {
        int r = idx >> 5, c4 = idx & 31;
        float4 v = ((const float4*)W1)[idx];
        split4(v, sBhi + r * LDS + c4 * 4, sBlo + r * LDS + c4 * 4);
    }
    __syncthreads();

    int w = tid >> 5, lane = tid & 31;
    int lr = lane & 15, lc = (lane >> 4) * 8;
    uint32_t aHi = sm_addr(sAhi + (w * 32 + lr) * LDS + lc);
    uint32_t aLo = sm_addr(sAlo + (w * 32 + lr) * LDS + lc);
    uint32_t bHi = sm_addr(sBhi + lr * LDS + lc);
    uint32_t bLo = sm_addr(sBlo + lr * LDS + lc);

    float acc[2][16][4];
#pragma unroll
    for (int c = 0; c < 2; c++)
#pragma unroll
        for (int t = 0; t < 16; t++)
#pragma unroll
            for (int i = 0; i < 4; i++) acc[c][t][i] = 0.f;

    // ---- layer 1 ----
    gemm_loop(aHi, aLo, bHi, bLo, acc);

    int grp = lane >> 2, tq = lane & 3;
#pragma unroll
    for (int c = 0; c < 2; c++)
#pragma unroll
    for (int t = 0; t < 16; t++) {
        int col = t * 8 + tq * 2;
        int r0 = w * 32 + c * 16 + grp, r1 = r0 + 8;
        float v0 = fmaxf(acc[c][t][0], 0.f), v1 = fmaxf(acc[c][t][1], 0.f);
        float v2 = fmaxf(acc[c][t][2], 0.f), v3 = fmaxf(acc[c][t][3], 0.f);
        __nv_bfloat16 h0 = __float2bfloat16_rn(v0), h1 = __float2bfloat16_rn(v1);
        __nv_bfloat16 h2 = __float2bfloat16_rn(v2), h3 = __float2bfloat16_rn(v3);
        __nv_bfloat162 p;
        p.x = h0; p.y = h1;
        *reinterpret_cast<__nv_bfloat162*>(&sAhi[r0 * LDS + col]) = p;
        p.x = h2; p.y = h3;
        *reinterpret_cast<__nv_bfloat162*>(&sAhi[r1 * LDS + col]) = p;
        p.x = __float2bfloat16_rn(v0 - __bfloat162float(h0));
        p.y = __float2bfloat16_rn(v1 - __bfloat162float(h1));
        *reinterpret_cast<__nv_bfloat162*>(&sAlo[r0 * LDS + col]) = p;
        p.x = __float2bfloat16_rn(v2 - __bfloat162float(h2));
        p.y = __float2bfloat16_rn(v3 - __bfloat162float(h3));
        *reinterpret_cast<__nv_bfloat162*>(&sAlo[r1 * LDS + col]) = p;
    }
    __syncthreads();

    for (int idx = tid; idx < 128 * 32; idx += 256) {
        int r = idx >> 5, c4 = idx & 31;
        float4 v = ((const float4*)W2)[idx];
        split4(v, sBhi + r * LDS + c4 * 4, sBlo + r * LDS + c4 * 4);
    }
    __syncthreads();

#pragma unroll
    for (int c = 0; c < 2; c++)
#pragma unroll
        for (int t = 0; t < 16; t++)
#pragma unroll
            for (int i = 0; i < 4; i++) acc[c][t][i] = 0.f;

    // ---- layer 2 ----
    gemm_loop(aHi, aLo, bHi, bLo, acc);

#pragma unroll
    for (int c = 0; c < 2; c++)
#pragma unroll
    for (int t = 0; t < 16; t++) {
        int col = t * 8 + tq * 2;
        int gm0 = m0 + w * 32 + c * 16 + grp;
        int gm1 = gm0 + 8;
        if (gm0 < M) {
            float2 o; o.x = acc[c][t][0]; o.y = acc[c][t][1];
            *reinterpret_cast<float2*>(&out[(size_t)gm0 * 128 + col]) = o;
        }
        if (gm1 < M) {
            float2 o; o.x = acc[c][t][2]; o.y = acc[c][t][3];
            *reinterpret_cast<float2*>(&out[(size_t)gm1 * 128 + col]) = o;
        }
    }
}

// ------- per-segment softmax + pooling + gate (chunked weights: V expf, not 128V) -------
__global__ void __launch_bounds__(128) k_pool(const int* __restrict__ csr,
                                              const float* __restrict__ gw,
                                              const float* __restrict__ gb,
                                              float* __restrict__ out,
                                              float* __restrict__ seen,
                                              int writeSeen) {
    int n = blockIdx.x;
    int s = csr[n], e = csr[n + 1];
    int tid = threadIdx.x;
    __shared__ float red[128];
    __shared__ float wgt[128];
    if (e <= s) {
        out[(size_t)n * 128 + tid] = 0.f;
        if (writeSeen && tid == 0) seen[n] = 0.f;
        return;
    }
    // segment max
    float m = -INFINITY;
    for (int v = s + tid; v < e; v += 128) m = fmaxf(m, g_comp[v]);
    red[tid] = m; __syncthreads();
#pragma unroll
    for (int off = 64; off > 0; off >>= 1) {
        if (tid < off) red[tid] = fmaxf(red[tid], red[tid + off]);
        __syncthreads();
    }
    m = red[0];
    __syncthreads();
    // chunked: one expf per view, weights broadcast via smem; sum folded in
    float acc = 0.f, esum = 0.f;
    for (int c0 = s; c0 < e; c0 += 128) {
        int cn = e - c0; if (cn > 128) cn = 128;
        if (tid < cn) {
            float wv = expf(g_comp[c0 + tid] - m);
            wgt[tid] = wv;
            esum += wv;
        }
        __syncthreads();
        for (int i = 0; i < cn; i++)
            acc += wgt[i] * g_hmod[(size_t)(c0 + i) * 128 + tid];
        __syncthreads();
    }
    red[tid] = esum; __syncthreads();
#pragma unroll
    for (int off = 64; off > 0; off >>= 1) {
        if (tid < off) red[tid] += red[tid + off];
        __syncthreads();
    }
    float sum = red[0];
    float gate = tanhf(fmaxf(gw[0] * m + gb[0], 0.f));
    out[(size_t)n * 128 + tid] = acc * (gate / (sum + 1e-12f));
    if (writeSeen && tid == 0) seen[n] = 1.f;
}

// ---------------- launch ----------------
extern "C" void kernel_launch(void* const* d_in, const int* in_sizes, int n_in,
                              void* d_out, int out_size) {
    const float* x_main  = (const float*)d_in[0];
    const float* x_mod   = (const float*)d_in[1];
    const float* x_map   = (const float*)d_in[2];
    const int*   csr     = (const int*)  d_in[3];
    const float* W_main1 = (const float*)d_in[4];
    const float* W_main2 = (const float*)d_in[5];
    const float* W_map1  = (const float*)d_in[6];
    const float* W_map2  = (const float*)d_in[7];
    const float* W_mod1  = (const float*)d_in[8];
    const float* W_mod2  = (const float*)d_in[9];
    const float* WQ      = (const float*)d_in[10];
    const float* bQ      = (const float*)d_in[11];
    const float* WK      = (const float*)d_in[12];
    const float* bK      = (const float*)d_in[13];
    const float* gw      = (const float*)d_in[14];
    const float* gb      = (const float*)d_in[15];

    int N = in_sizes[3] - 1;
    int V = in_sizes[2] / 16;

    float* out = (float*)d_out;
    float* seen = nullptr;
    int writeSeen = 0;
    long long written = (long long)N * 128;
    if ((long long)out_size >= (long long)N * 128 + N) {
        seen = out + (size_t)N * 128;
        writeSeen = 1;
        written += N;
    }

    void* hmodPtr = nullptr;
    cudaGetSymbolAddress(&hmodPtr, g_hmod);
    float* hmod = (float*)hmodPtr;

    k_zero_ctx<<<(N * 32 + 255) / 256, 256>>>(N * 32);
    k_didx<<<(V + 255) / 256, 256>>>(csr, N, V);
    k_q<<<(N + 7) / 8, 256>>>(x_main, W_main1, W_main2, WQ, bQ, N);
    k_h<<<(V + 31) / 32, 256>>>(x_map, W_map1, V);
    k_ctx2<<<(N + 7) / 8, 256>>>(W_map2, N);
    k_comp<<<(V + 31) / 32, 256>>>(W_map2, WK, bK, V);

    cudaFuncSetAttribute(k_fused_mod, cudaFuncAttributeMaxDynamicSharedMemorySize, FUSED_SMEM);
    k_fused_mod<<<(V + MT - 1) / MT, 256, FUSED_SMEM>>>(x_mod, W_mod1, W_mod2, hmod, V);

    k_pool<<<N, 128>>>(csr, gw, gb, out, seen, writeSeen);

    long long tail = (long long)out_size - written;
    if (tail > 0) {
        k_tail_zero<<<(int)((tail + 255) / 256), 256>>>(out + written, (int)tail);
    }
}

// round 14
// speedup vs baseline: 1.0833x; 1.0028x over previous
#include <cuda_runtime.h>
#include <cuda_bf16.h>
#include <cstdint>
#include <math.h>

#define NPTS  50000
#define NVIEW 500000
#define LDS   136   // 128 + 8 bf16 padding -> conflict-free ldmatrix

// ---------------- scratch (device globals; no allocations) ----------------
__device__ int   g_didx[NVIEW];
__device__ float g_q[NPTS * 8];
__device__ float g_h[(size_t)NVIEW * 32];
__device__ float g_ctx[NPTS * 32];
__device__ float g_c2[NPTS * 32];          // ctx @ W2_bottom, per segment
__device__ float g_comp[NVIEW];
__device__ float g_hmod[(size_t)NVIEW * 128];

// ---------------- small utility kernels ----------------
__global__ void k_zero_ctx(int n) {
    int i = blockIdx.x * blockDim.x + threadIdx.x;
    if (i < n) g_ctx[i] = 0.0f;
}
__global__ void k_tail_zero(float* p, int n) {
    int i = blockIdx.x * blockDim.x + threadIdx.x;
    if (i < n) p[i] = 0.0f;
}

__global__ void k_didx(const int* __restrict__ csr, int N, int V) {
    int v = blockIdx.x * blockDim.x + threadIdx.x;
    if (v >= V) return;
    int lo = 0, hi = N - 1;
    while (lo < hi) {
        int mid = (lo + hi) >> 1;
        if (csr[mid + 1] <= v) lo = mid + 1; else hi = mid;
    }
    g_didx[v] = lo;
}

// ---------------- per-point queries (4 points/warp, staged weights amortized) ----------------
__global__ void __launch_bounds__(256) k_q(const float* __restrict__ xm,
                                           const float* __restrict__ W1,
                                           const float* __restrict__ W2,
                                           const float* __restrict__ WQ,
                                           const float* __restrict__ bQ, int N) {
    __shared__ float sW1[64 * 32];
    __shared__ float sW2[32 * 32];
    __shared__ float sWQ[32 * 8];
    __shared__ __align__(16) float sxq[8][260];   // 4 points x 64 (+pad)
    __shared__ float s1[8][36];
    __shared__ float s2[8][36];
    int tid = threadIdx.x;
    for (int i = tid; i < 64 * 32; i += 256) sW1[i] = W1[i];
    for (int i = tid; i < 32 * 32; i += 256) sW2[i] = W2[i];
    for (int i = tid; i < 32 * 8;  i += 256) sWQ[i] = WQ[i];
    __syncthreads();
    int w = tid >> 5, j = tid & 31;
    int p0 = (blockIdx.x * 8 + w) * 4;
    if (p0 >= N) return;
    int np = N - p0; if (np > 4) np = 4;

    if (p0 + 3 < N) {
        const float4* src = (const float4*)(xm + (size_t)p0 * 64);
        float4 t0 = src[j], t1 = src[j + 32];
        *(float4*)&sxq[w][j * 4]       = t0;
        *(float4*)&sxq[w][128 + j * 4] = t1;
    } else {
        for (int idx = j; idx < np * 64; idx += 32)
            sxq[w][idx] = xm[(size_t)p0 * 64 + idx];
    }
    __syncwarp();

    for (int u = 0; u < np; u++) {
        float acc = 0.f;
#pragma unroll
        for (int i = 0; i < 64; i++) acc += sxq[w][u * 64 + i] * sW1[i * 32 + j];
        s1[w][j] = fmaxf(acc, 0.f);
        __syncwarp();
        acc = 0.f;
#pragma unroll
        for (int i = 0; i < 32; i++) acc += s1[w][i] * sW2[i * 32 + j];
        s2[w][j] = acc;
        __syncwarp();
        if (j < 8) {
            acc = bQ[j];
#pragma unroll
            for (int i = 0; i < 32; i++) acc += s2[w][i] * sWQ[i * 8 + j];
            g_q[(size_t)(p0 + u) * 8 + j] = acc;
        }
        __syncwarp();
    }
}

// ------ per-view h = relu(x_map@W_map1); 8 views/warp (2 passes of 4), aggregated seg-max ------
__global__ void __launch_bounds__(256) k_h(const float* __restrict__ xmap,
                                           const float* __restrict__ W1, int V) {
    __shared__ float sW[16 * 32];
    __shared__ __align__(16) float sx[8][68];     // 4 views x 16 floats (+pad)
    int tid = threadIdx.x;
    for (int i = tid; i < 16 * 32; i += 256) sW[i] = W1[i];
    __syncthreads();
    int w = tid >> 5, j = tid & 31;
    int vbase = (blockIdx.x * 8 + w) * 8;

    for (int pass = 0; pass < 2; pass++) {
        int v0 = vbase + pass * 4;
        if (v0 >= V) break;
        int nv = V - v0; if (nv > 4) nv = 4;

        if (v0 + 3 < V) {
            if (j < 16) {
                float4 t = ((const float4*)xmap)[(size_t)v0 * 4 + j];
                float* d = &sx[w][j * 4];
                d[0] = t.x; d[1] = t.y; d[2] = t.z; d[3] = t.w;
            }
        } else {
            for (int idx = j; idx < nv * 16; idx += 32)
                sx[w][idx] = xmap[(size_t)v0 * 16 + idx];
        }
        __syncwarp();

        float h[4];
        int seg[4];
#pragma unroll
        for (int u = 0; u < 4; u++) {
            if (u < nv) {
                float acc = 0.f;
#pragma unroll
                for (int i = 0; i < 16; i++) acc += sx[w][u * 16 + i] * sW[i * 32 + j];
                h[u] = fmaxf(acc, 0.f);
                g_h[(size_t)(v0 + u) * 32 + j] = h[u];
                seg[u] = g_didx[v0 + u];
            }
        }
        float m = h[0]; int cs = seg[0];
#pragma unroll
        for (int u = 1; u < 4; u++) {
            if (u < nv) {
                if (seg[u] == cs) m = fmaxf(m, h[u]);
                else {
                    atomicMax((int*)&g_ctx[cs * 32 + j], __float_as_int(m));
                    cs = seg[u]; m = h[u];
                }
            }
        }
        atomicMax((int*)&g_ctx[cs * 32 + j], __float_as_int(m));
        __syncwarp();
    }
}

// -------- per-segment: c2 = ctx @ W2[32:64] (the ctx half of the concat matvec) --------
__global__ void __launch_bounds__(256) k_ctx2(const float* __restrict__ W2, int N) {
    __shared__ float sW[32 * 32];
    __shared__ float sx[8][32];
    int tid = threadIdx.x;
    for (int i = tid; i < 32 * 32; i += 256) sW[i] = W2[32 * 32 + i];  // rows 32..63
    __syncthreads();
    int w = tid >> 5, j = tid & 31;
    int p = blockIdx.x * 8 + w;
    if (p >= N) return;
    sx[w][j] = g_ctx[p * 32 + j];
    __syncwarp();
    float acc = 0.f;
#pragma unroll
    for (int i = 0; i < 32; i++) acc += sx[w][i] * sW[i * 32 + j];
    g_c2[p * 32 + j] = acc;
}

// ---------------- per-view comp (8 views/warp in 2 passes, parallel key groups) ----------------
__global__ void __launch_bounds__(256) k_comp(const float* __restrict__ W2,
                                              const float* __restrict__ WK,
                                              const float* __restrict__ bK, int V) {
    __shared__ float sW[32 * 32];
    __shared__ float sWK[32 * 8];
    __shared__ __align__(16) float cat[8][132];
    __shared__ float kv[8][132];
    int tid = threadIdx.x;
    for (int i = tid; i < 32 * 32; i += 256) sW[i] = W2[i];          // rows 0..31 (h part)
    for (int i = tid; i < 32 * 8;  i += 256) sWK[i] = WK[i];
    __syncthreads();
    int w = tid >> 5, j = tid & 31;
    int vbase = (blockIdx.x * 8 + w) * 8;

    for (int pass = 0; pass < 2; pass++) {
        int v0 = vbase + pass * 4;
        if (v0 >= V) break;
        int nv = V - v0; if (nv > 4) nv = 4;

        if (v0 + 3 < V) {
            float4 t = ((const float4*)(g_h + (size_t)v0 * 32))[j];
            float* d = &cat[w][j * 4];
            d[0] = t.x; d[1] = t.y; d[2] = t.z; d[3] = t.w;
        } else {
            for (int idx = j; idx < nv * 32; idx += 32)
                cat[w][idx] = g_h[(size_t)v0 * 32 + idx];
        }
        __syncwarp();

#pragma unroll
        for (int u = 0; u < 4; u++) {
            if (u < nv) {
                int sg = g_didx[v0 + u];
                float acc = g_c2[sg * 32 + j];
#pragma unroll
                for (int i = 0; i < 32; i++) acc += cat[w][u * 32 + i] * sW[i * 32 + j];
                kv[w][u * 32 + j] = fmaxf(acc, 0.f);
            }
        }
        __syncwarp();

        int u = j >> 3, jq = j & 7;
        float c = 0.f;
        if (u < nv) {
            int segu = g_didx[v0 + u];
            float key = bK[jq];
#pragma unroll
            for (int i = 0; i < 32; i++) key += kv[w][u * 32 + i] * sWK[i * 8 + jq];
            c = key * g_q[(size_t)segu * 8 + jq];
        }
        c += __shfl_down_sync(0xffffffff, c, 4, 8);
        c += __shfl_down_sync(0xffffffff, c, 2, 8);
        c += __shfl_down_sync(0xffffffff, c, 1, 8);
        if (jq == 0 && u < nv) g_comp[v0 + u] = c * 0.35355339059327373f;
        __syncwarp();
    }
}

// ---------------- tensor-core fused 2-layer GEMM (split-bf16, 3-MMA, M=256) ----------------
__device__ __forceinline__ uint32_t sm_addr(const void* p) {
    return (uint32_t)__cvta_generic_to_shared(p);
}
__device__ __forceinline__ void ldsm4(uint32_t a, uint32_t* r) {
    asm volatile("ldmatrix.sync.aligned.m8n8.x4.shared.b16 {%0,%1,%2,%3}, [%4];"
                 : "=r"(r[0]), "=r"(r[1]), "=r"(r[2]), "=r"(r[3]) : "r"(a));
}
__device__ __forceinline__ void ldsm4t(uint32_t a, uint32_t* r) {
    asm volatile("ldmatrix.sync.aligned.m8n8.x4.trans.shared.b16 {%0,%1,%2,%3}, [%4];"
                 : "=r"(r[0]), "=r"(r[1]), "=r"(r[2]), "=r"(r[3]) : "r"(a));
}
__device__ __forceinline__ void mma16816(float* d, const uint32_t* a, uint32_t b0, uint32_t b1) {
    asm volatile("mma.sync.aligned.m16n8k16.row.col.f32.bf16.bf16.f32 "
                 "{%0,%1,%2,%3}, {%4,%5,%6,%7}, {%8,%9}, {%0,%1,%2,%3};"
                 : "+f"(d[0]), "+f"(d[1]), "+f"(d[2]), "+f"(d[3])
                 : "r"(a[0]), "r"(a[1]), "r"(a[2]), "r"(a[3]), "r"(b0), "r"(b1));
}
__device__ __forceinline__ void split4(float4 v, __nv_bfloat16* hi, __nv_bfloat16* lo) {
    float f[4] = {v.x, v.y, v.z, v.w};
    __nv_bfloat162 h01, h23, l01, l23;
    __nv_bfloat16 h0 = __float2bfloat16_rn(f[0]);
    __nv_bfloat16 h1 = __float2bfloat16_rn(f[1]);
    __nv_bfloat16 h2 = __float2bfloat16_rn(f[2]);
    __nv_bfloat16 h3 = __float2bfloat16_rn(f[3]);
    h01.x = h0; h01.y = h1; h23.x = h2; h23.y = h3;
    l01.x = __float2bfloat16_rn(f[0] - __bfloat162float(h0));
    l01.y = __float2bfloat16_rn(f[1] - __bfloat162float(h1));
    l23.x = __float2bfloat16_rn(f[2] - __bfloat162float(h2));
    l23.y = __float2bfloat16_rn(f[3] - __bfloat162float(h3));
    *reinterpret_cast<__nv_bfloat162*>(hi)     = h01;
    *reinterpret_cast<__nv_bfloat162*>(hi + 2) = h23;
    *reinterpret_cast<__nv_bfloat162*>(lo)     = l01;
    *reinterpret_cast<__nv_bfloat162*>(lo + 2) = l23;
}

// acc layout: acc[c][t][4]; A and B fragments double-buffered; ks fully unrolled.
__device__ __forceinline__ void gemm_loop(uint32_t aHi0, uint32_t aLo0,
                                          uint32_t bHi, uint32_t bLo,
                                          float (&acc)[2][16][4]) {
    const uint32_t CH = 16 * LDS * 2;
    uint32_t ah[2][2][4], al[2][2][4];
    ldsm4(aHi0,      ah[0][0]);
    ldsm4(aLo0,      al[0][0]);
    ldsm4(aHi0 + CH, ah[0][1]);
    ldsm4(aLo0 + CH, al[0][1]);
#pragma unroll
    for (int ks = 0; ks < 8; ks++) {
        const int cab = ks & 1, nab = cab ^ 1;
        if (ks < 7) {
            ldsm4(aHi0 + (ks + 1) * 32,      ah[nab][0]);
            ldsm4(aLo0 + (ks + 1) * 32,      al[nab][0]);
            ldsm4(aHi0 + CH + (ks + 1) * 32, ah[nab][1]);
            ldsm4(aLo0 + CH + (ks + 1) * 32, al[nab][1]);
        }
        uint32_t bBaseH = bHi + (uint32_t)(ks * 16 * LDS) * 2u;
        uint32_t bBaseL = bLo + (uint32_t)(ks * 16 * LDS) * 2u;
        uint32_t bh[2][4], bl[2][4];
        ldsm4t(bBaseH, bh[0]);
        ldsm4t(bBaseL, bl[0]);
#pragma unroll
        for (int np = 0; np < 8; np++) {
            const int cur = np & 1, nxt = cur ^ 1;
            if (np < 7) {
                ldsm4t(bBaseH + (np + 1) * 32, bh[nxt]);
                ldsm4t(bBaseL + (np + 1) * 32, bl[nxt]);
            }
#pragma unroll
            for (int c = 0; c < 2; c++) {
                mma16816(acc[c][np * 2],     ah[cab][c], bh[cur][0], bh[cur][1]);
                mma16816(acc[c][np * 2 + 1], ah[cab][c], bh[cur][2], bh[cur][3]);
                mma16816(acc[c][np * 2],     ah[cab][c], bl[cur][0], bl[cur][1]);
                mma16816(acc[c][np * 2 + 1], ah[cab][c], bl[cur][2], bl[cur][3]);
                mma16816(acc[c][np * 2],     al[cab][c], bh[cur][0], bh[cur][1]);
                mma16816(acc[c][np * 2 + 1], al[cab][c], bh[cur][2], bh[cur][3]);
            }
        }
    }
}

#define MT 256                              // M tile
#define FUSED_SMEM ((2 * MT + 2 * 128) * LDS * 2)

// out[M,128] = relu(X[M,128] @ W1) @ W2
__global__ void __launch_bounds__(256, 1) k_fused_mod(const float* __restrict__ X,
                                                      const float* __restrict__ W1,
                                                      const float* __restrict__ W2,
                                                      float* __restrict__ out, int M) {
    extern __shared__ __nv_bfloat16 sm[];
    __nv_bfloat16* sAhi = sm;
    __nv_bfloat16* sAlo = sm + (size_t)MT * LDS;
    __nv_bfloat16* sBhi = sm + (size_t)2 * MT * LDS;
    __nv_bfloat16* sBlo = sBhi + (size_t)128 * LDS;

    int tid = threadIdx.x;
    int m0 = blockIdx.x * MT;

    for (int idx = tid; idx < MT * 32; idx += 256) {
        int r = idx >> 5, c4 = idx & 31;
        float4 v = (m0 + r < M) ? ((const float4*)X)[(size_t)(m0 + r) * 32 + c4]
                                : make_float4(0.f, 0.f, 0.f, 0.f);
        split4(v, sAhi + r * LDS + c4 * 4, sAlo + r * LDS + c4 * 4);
    }
    for (int idx = tid; idx < 128 * 32; idx += 256) {
        int r = idx >> 5, c4 = idx & 31;
        float4 v = ((const float4*)W1)[idx];
        split4(v, sBhi + r * LDS + c4 * 4, sBlo + r * LDS + c4 * 4);
    }
    __syncthreads();

    int w = tid >> 5, lane = tid & 31;
    int lr = lane & 15, lc = (lane >> 4) * 8;
    uint32_t aHi = sm_addr(sAhi + (w * 32 + lr) * LDS + lc);
    uint32_t aLo = sm_addr(sAlo + (w * 32 + lr) * LDS + lc);
    uint32_t bHi = sm_addr(sBhi + lr * LDS + lc);
    uint32_t bLo = sm_addr(sBlo + lr * LDS + lc);

    float acc[2][16][4];
#pragma unroll
    for (int c = 0; c < 2; c++)
#pragma unroll
        for (int t = 0; t < 16; t++)
#pragma unroll
            for (int i = 0; i < 4; i++) acc[c][t][i] = 0.f;

    // ---- layer 1 ----
    gemm_loop(aHi, aLo, bHi, bLo, acc);

    int grp = lane >> 2, tq = lane & 3;
#pragma unroll
    for (int c = 0; c < 2; c++)
#pragma unroll
    for (int t = 0; t < 16; t++) {
        int col = t * 8 + tq * 2;
        int r0 = w * 32 + c * 16 + grp, r1 = r0 + 8;
        float v0 = fmaxf(acc[c][t][0], 0.f), v1 = fmaxf(acc[c][t][1], 0.f);
        float v2 = fmaxf(acc[c][t][2], 0.f), v3 = fmaxf(acc[c][t][3], 0.f);
        __nv_bfloat16 h0 = __float2bfloat16_rn(v0), h1 = __float2bfloat16_rn(v1);
        __nv_bfloat16 h2 = __float2bfloat16_rn(v2), h3 = __float2bfloat16_rn(v3);
        __nv_bfloat162 p;
        p.x = h0; p.y = h1;
        *reinterpret_cast<__nv_bfloat162*>(&sAhi[r0 * LDS + col]) = p;
        p.x = h2; p.y = h3;
        *reinterpret_cast<__nv_bfloat162*>(&sAhi[r1 * LDS + col]) = p;
        p.x = __float2bfloat16_rn(v0 - __bfloat162float(h0));
        p.y = __float2bfloat16_rn(v1 - __bfloat162float(h1));
        *reinterpret_cast<__nv_bfloat162*>(&sAlo[r0 * LDS + col]) = p;
        p.x = __float2bfloat16_rn(v2 - __bfloat162float(h2));
        p.y = __float2bfloat16_rn(v3 - __bfloat162float(h3));
        *reinterpret_cast<__nv_bfloat162*>(&sAlo[r1 * LDS + col]) = p;
    }
    __syncthreads();

    for (int idx = tid; idx < 128 * 32; idx += 256) {
        int r = idx >> 5, c4 = idx & 31;
        float4 v = ((const float4*)W2)[idx];
        split4(v, sBhi + r * LDS + c4 * 4, sBlo + r * LDS + c4 * 4);
    }
    __syncthreads();

#pragma unroll
    for (int c = 0; c < 2; c++)
#pragma unroll
        for (int t = 0; t < 16; t++)
#pragma unroll
            for (int i = 0; i < 4; i++) acc[c][t][i] = 0.f;

    // ---- layer 2 ----
    gemm_loop(aHi, aLo, bHi, bLo, acc);

#pragma unroll
    for (int c = 0; c < 2; c++)
#pragma unroll
    for (int t = 0; t < 16; t++) {
        int col = t * 8 + tq * 2;
        int gm0 = m0 + w * 32 + c * 16 + grp;
        int gm1 = gm0 + 8;
        if (gm0 < M) {
            float2 o; o.x = acc[c][t][0]; o.y = acc[c][t][1];
            *reinterpret_cast<float2*>(&out[(size_t)gm0 * 128 + col]) = o;
        }
        if (gm1 < M) {
            float2 o; o.x = acc[c][t][2]; o.y = acc[c][t][3];
            *reinterpret_cast<float2*>(&out[(size_t)gm1 * 128 + col]) = o;
        }
    }
}

// ------- per-segment softmax + pooling + gate (chunked weights: V expf, not 128V) -------
__global__ void __launch_bounds__(128) k_pool(const int* __restrict__ csr,
                                              const float* __restrict__ gw,
                                              const float* __restrict__ gb,
                                              float* __restrict__ out,
                                              float* __restrict__ seen,
                                              int writeSeen) {
    int n = blockIdx.x;
    int s = csr[n], e = csr[n + 1];
    int tid = threadIdx.x;
    __shared__ float red[128];
    __shared__ float wgt[128];
    if (e <= s) {
        out[(size_t)n * 128 + tid] = 0.f;
        if (writeSeen && tid == 0) seen[n] = 0.f;
        return;
    }
    float m = -INFINITY;
    for (int v = s + tid; v < e; v += 128) m = fmaxf(m, g_comp[v]);
    red[tid] = m; __syncthreads();
#pragma unroll
    for (int off = 64; off > 0; off >>= 1) {
        if (tid < off) red[tid] = fmaxf(red[tid], red[tid + off]);
        __syncthreads();
    }
    m = red[0];
    __syncthreads();
    float acc = 0.f, esum = 0.f;
    for (int c0 = s; c0 < e; c0 += 128) {
        int cn = e - c0; if (cn > 128) cn = 128;
        if (tid < cn) {
            float wv = expf(g_comp[c0 + tid] - m);
            wgt[tid] = wv;
            esum += wv;
        }
        __syncthreads();
        for (int i = 0; i < cn; i++)
            acc += wgt[i] * g_hmod[(size_t)(c0 + i) * 128 + tid];
        __syncthreads();
    }
    red[tid] = esum; __syncthreads();
#pragma unroll
    for (int off = 64; off > 0; off >>= 1) {
        if (tid < off) red[tid] += red[tid + off];
        __syncthreads();
    }
    float sum = red[0];
    float gate = tanhf(fmaxf(gw[0] * m + gb[0], 0.f));
    out[(size_t)n * 128 + tid] = acc * (gate / (sum + 1e-12f));
    if (writeSeen && tid == 0) seen[n] = 1.f;
}

// ---------------- launch ----------------
extern "C" void kernel_launch(void* const* d_in, const int* in_sizes, int n_in,
                              void* d_out, int out_size) {
    const float* x_main  = (const float*)d_in[0];
    const float* x_mod   = (const float*)d_in[1];
    const float* x_map   = (const float*)d_in[2];
    const int*   csr     = (const int*)  d_in[3];
    const float* W_main1 = (const float*)d_in[4];
    const float* W_main2 = (const float*)d_in[5];
    const float* W_map1  = (const float*)d_in[6];
    const float* W_map2  = (const float*)d_in[7];
    const float* W_mod1  = (const float*)d_in[8];
    const float* W_mod2  = (const float*)d_in[9];
    const float* WQ      = (const float*)d_in[10];
    const float* bQ      = (const float*)d_in[11];
    const float* WK      = (const float*)d_in[12];
    const float* bK      = (const float*)d_in[13];
    const float* gw      = (const float*)d_in[14];
    const float* gb      = (const float*)d_in[15];

    int N = in_sizes[3] - 1;
    int V = in_sizes[2] / 16;

    float* out = (float*)d_out;
    float* seen = nullptr;
    int writeSeen = 0;
    long long written = (long long)N * 128;
    if ((long long)out_size >= (long long)N * 128 + N) {
        seen = out + (size_t)N * 128;
        writeSeen = 1;
        written += N;
    }

    void* hmodPtr = nullptr;
    cudaGetSymbolAddress(&hmodPtr, g_hmod);
    float* hmod = (float*)hmodPtr;

    k_zero_ctx<<<(N * 32 + 255) / 256, 256>>>(N * 32);
    k_didx<<<(V + 255) / 256, 256>>>(csr, N, V);
    k_q<<<(N + 31) / 32, 256>>>(x_main, W_main1, W_main2, WQ, bQ, N);
    k_h<<<(V + 63) / 64, 256>>>(x_map, W_map1, V);
    k_ctx2<<<(N + 7) / 8, 256>>>(W_map2, N);
    k_comp<<<(V + 63) / 64, 256>>>(W_map2, WK, bK, V);

    cudaFuncSetAttribute(k_fused_mod, cudaFuncAttributeMaxDynamicSharedMemorySize, FUSED_SMEM);
    k_fused_mod<<<(V + MT - 1) / MT, 256, FUSED_SMEM>>>(x_mod, W_mod1, W_mod2, hmod, V);

    k_pool<<<N, 128>>>(csr, gw, gb, out, seen, writeSeen);

    long long tail = (long long)out_size - written;
    if (tail > 0) {
        k_tail_zero<<<(int)((tail + 255) / 256), 256>>>(out + written, (int)tail);
    }
}

// round 15
// speedup vs baseline: 1.2699x; 1.1722x over previous
#include <cuda_runtime.h>
#include <cuda_bf16.h>
#include <cstdint>
#include <math.h>

#define NPTS  50000
#define NVIEW 500000
#define LDS   136   // 128 + 8 bf16 padding -> conflict-free ldmatrix

// ---------------- scratch (device globals; no allocations) ----------------
__device__ int   g_didx[NVIEW];
__device__ float g_q[NPTS * 8];
__device__ float g_h[(size_t)NVIEW * 32];
__device__ float g_ctx[NPTS * 32];
__device__ float g_c2[NPTS * 32];
__device__ float g_comp[NVIEW];
__device__ float g_att[NVIEW];             // softmax * gate, per view
__device__ float g_pool1[(size_t)NPTS * 128]; // segment-pooled relu(x@W1)

// ---------------- small utility kernels ----------------
__global__ void k_zero_ctx(int n) {
    int i = blockIdx.x * blockDim.x + threadIdx.x;
    if (i < n) g_ctx[i] = 0.0f;
}
__global__ void k_zero_pool1(int n) {
    int i = blockIdx.x * blockDim.x + threadIdx.x;
    if (i < n) g_pool1[i] = 0.0f;
}
__global__ void k_tail_zero(float* p, int n) {
    int i = blockIdx.x * blockDim.x + threadIdx.x;
    if (i < n) p[i] = 0.0f;
}

__global__ void k_didx(const int* __restrict__ csr, int N, int V) {
    int v = blockIdx.x * blockDim.x + threadIdx.x;
    if (v >= V) return;
    int lo = 0, hi = N - 1;
    while (lo < hi) {
        int mid = (lo + hi) >> 1;
        if (csr[mid + 1] <= v) lo = mid + 1; else hi = mid;
    }
    g_didx[v] = lo;
}

// ---------------- per-point queries (4 points/warp) ----------------
__global__ void __launch_bounds__(256) k_q(const float* __restrict__ xm,
                                           const float* __restrict__ W1,
                                           const float* __restrict__ W2,
                                           const float* __restrict__ WQ,
                                           const float* __restrict__ bQ, int N) {
    __shared__ float sW1[64 * 32];
    __shared__ float sW2[32 * 32];
    __shared__ float sWQ[32 * 8];
    __shared__ __align__(16) float sxq[8][260];
    __shared__ float s1[8][36];
    __shared__ float s2[8][36];
    int tid = threadIdx.x;
    for (int i = tid; i < 64 * 32; i += 256) sW1[i] = W1[i];
    for (int i = tid; i < 32 * 32; i += 256) sW2[i] = W2[i];
    for (int i = tid; i < 32 * 8;  i += 256) sWQ[i] = WQ[i];
    __syncthreads();
    int w = tid >> 5, j = tid & 31;
    int p0 = (blockIdx.x * 8 + w) * 4;
    if (p0 >= N) return;
    int np = N - p0; if (np > 4) np = 4;

    if (p0 + 3 < N) {
        const float4* src = (const float4*)(xm + (size_t)p0 * 64);
        float4 t0 = src[j], t1 = src[j + 32];
        *(float4*)&sxq[w][j * 4]       = t0;
        *(float4*)&sxq[w][128 + j * 4] = t1;
    } else {
        for (int idx = j; idx < np * 64; idx += 32)
            sxq[w][idx] = xm[(size_t)p0 * 64 + idx];
    }
    __syncwarp();

    for (int u = 0; u < np; u++) {
        float acc = 0.f;
#pragma unroll
        for (int i = 0; i < 64; i++) acc += sxq[w][u * 64 + i] * sW1[i * 32 + j];
        s1[w][j] = fmaxf(acc, 0.f);
        __syncwarp();
        acc = 0.f;
#pragma unroll
        for (int i = 0; i < 32; i++) acc += s1[w][i] * sW2[i * 32 + j];
        s2[w][j] = acc;
        __syncwarp();
        if (j < 8) {
            acc = bQ[j];
#pragma unroll
            for (int i = 0; i < 32; i++) acc += s2[w][i] * sWQ[i * 8 + j];
            g_q[(size_t)(p0 + u) * 8 + j] = acc;
        }
        __syncwarp();
    }
}

// ------ per-view h = relu(x_map@W_map1); 8 views/warp, aggregated seg-max ------
__global__ void __launch_bounds__(256) k_h(const float* __restrict__ xmap,
                                           const float* __restrict__ W1, int V) {
    __shared__ float sW[16 * 32];
    __shared__ __align__(16) float sx[8][68];
    int tid = threadIdx.x;
    for (int i = tid; i < 16 * 32; i += 256) sW[i] = W1[i];
    __syncthreads();
    int w = tid >> 5, j = tid & 31;
    int vbase = (blockIdx.x * 8 + w) * 8;

    for (int pass = 0; pass < 2; pass++) {
        int v0 = vbase + pass * 4;
        if (v0 >= V) break;
        int nv = V - v0; if (nv > 4) nv = 4;

        if (v0 + 3 < V) {
            if (j < 16) {
                float4 t = ((const float4*)xmap)[(size_t)v0 * 4 + j];
                float* d = &sx[w][j * 4];
                d[0] = t.x; d[1] = t.y; d[2] = t.z; d[3] = t.w;
            }
        } else {
            for (int idx = j; idx < nv * 16; idx += 32)
                sx[w][idx] = xmap[(size_t)v0 * 16 + idx];
        }
        __syncwarp();

        float h[4];
        int seg[4];
#pragma unroll
        for (int u = 0; u < 4; u++) {
            if (u < nv) {
                float acc = 0.f;
#pragma unroll
                for (int i = 0; i < 16; i++) acc += sx[w][u * 16 + i] * sW[i * 32 + j];
                h[u] = fmaxf(acc, 0.f);
                g_h[(size_t)(v0 + u) * 32 + j] = h[u];
                seg[u] = g_didx[v0 + u];
            }
        }
        float m = h[0]; int cs = seg[0];
#pragma unroll
        for (int u = 1; u < 4; u++) {
            if (u < nv) {
                if (seg[u] == cs) m = fmaxf(m, h[u]);
                else {
                    atomicMax((int*)&g_ctx[cs * 32 + j], __float_as_int(m));
                    cs = seg[u]; m = h[u];
                }
            }
        }
        atomicMax((int*)&g_ctx[cs * 32 + j], __float_as_int(m));
        __syncwarp();
    }
}

// -------- per-segment: c2 = ctx @ W2[32:64] --------
__global__ void __launch_bounds__(256) k_ctx2(const float* __restrict__ W2, int N) {
    __shared__ float sW[32 * 32];
    __shared__ float sx[8][32];
    int tid = threadIdx.x;
    for (int i = tid; i < 32 * 32; i += 256) sW[i] = W2[32 * 32 + i];
    __syncthreads();
    int w = tid >> 5, j = tid & 31;
    int p = blockIdx.x * 8 + w;
    if (p >= N) return;
    sx[w][j] = g_ctx[p * 32 + j];
    __syncwarp();
    float acc = 0.f;
#pragma unroll
    for (int i = 0; i < 32; i++) acc += sx[w][i] * sW[i * 32 + j];
    g_c2[p * 32 + j] = acc;
}

// ---------------- per-view comp (8 views/warp in 2 passes) ----------------
__global__ void __launch_bounds__(256) k_comp(const float* __restrict__ W2,
                                              const float* __restrict__ WK,
                                              const float* __restrict__ bK, int V) {
    __shared__ float sW[32 * 32];
    __shared__ float sWK[32 * 8];
    __shared__ __align__(16) float cat[8][132];
    __shared__ float kv[8][132];
    int tid = threadIdx.x;
    for (int i = tid; i < 32 * 32; i += 256) sW[i] = W2[i];
    for (int i = tid; i < 32 * 8;  i += 256) sWK[i] = WK[i];
    __syncthreads();
    int w = tid >> 5, j = tid & 31;
    int vbase = (blockIdx.x * 8 + w) * 8;

    for (int pass = 0; pass < 2; pass++) {
        int v0 = vbase + pass * 4;
        if (v0 >= V) break;
        int nv = V - v0; if (nv > 4) nv = 4;

        if (v0 + 3 < V) {
            float4 t = ((const float4*)(g_h + (size_t)v0 * 32))[j];
            float* d = &cat[w][j * 4];
            d[0] = t.x; d[1] = t.y; d[2] = t.z; d[3] = t.w;
        } else {
            for (int idx = j; idx < nv * 32; idx += 32)
                cat[w][idx] = g_h[(size_t)v0 * 32 + idx];
        }
        __syncwarp();

#pragma unroll
        for (int u = 0; u < 4; u++) {
            if (u < nv) {
                int sg = g_didx[v0 + u];
                float acc = g_c2[sg * 32 + j];
#pragma unroll
                for (int i = 0; i < 32; i++) acc += cat[w][u * 32 + i] * sW[i * 32 + j];
                kv[w][u * 32 + j] = fmaxf(acc, 0.f);
            }
        }
        __syncwarp();

        int u = j >> 3, jq = j & 7;
        float c = 0.f;
        if (u < nv) {
            int segu = g_didx[v0 + u];
            float key = bK[jq];
#pragma unroll
            for (int i = 0; i < 32; i++) key += kv[w][u * 32 + i] * sWK[i * 8 + jq];
            c = key * g_q[(size_t)segu * 8 + jq];
        }
        c += __shfl_down_sync(0xffffffff, c, 4, 8);
        c += __shfl_down_sync(0xffffffff, c, 2, 8);
        c += __shfl_down_sync(0xffffffff, c, 1, 8);
        if (jq == 0 && u < nv) g_comp[v0 + u] = c * 0.35355339059327373f;
        __syncwarp();
    }
}

// ------- per-segment softmax + gate -> per-view attention weight g_att -------
__global__ void __launch_bounds__(128) k_att(const int* __restrict__ csr,
                                             const float* __restrict__ gw,
                                             const float* __restrict__ gb,
                                             float* __restrict__ seen,
                                             int writeSeen) {
    int n = blockIdx.x;
    int s = csr[n], e = csr[n + 1];
    int tid = threadIdx.x;
    __shared__ float red[128];
    if (e <= s) {
        if (writeSeen && tid == 0) seen[n] = 0.f;
        return;
    }
    float m = -INFINITY;
    for (int v = s + tid; v < e; v += 128) m = fmaxf(m, g_comp[v]);
    red[tid] = m; __syncthreads();
#pragma unroll
    for (int off = 64; off > 0; off >>= 1) {
        if (tid < off) red[tid] = fmaxf(red[tid], red[tid + off]);
        __syncthreads();
    }
    m = red[0];
    __syncthreads();
    float sum = 0.f;
    for (int v = s + tid; v < e; v += 128) sum += expf(g_comp[v] - m);
    red[tid] = sum; __syncthreads();
#pragma unroll
    for (int off = 64; off > 0; off >>= 1) {
        if (tid < off) red[tid] += red[tid + off];
        __syncthreads();
    }
    float gate = tanhf(fmaxf(gw[0] * m + gb[0], 0.f));
    float winv = gate / (red[0] + 1e-12f);
    for (int v = s + tid; v < e; v += 128)
        g_att[v] = expf(g_comp[v] - m) * winv;
    if (writeSeen && tid == 0) seen[n] = 1.f;
}

// ---------------- tensor-core GEMM machinery (split-bf16, 3-MMA, M=256) ----------------
__device__ __forceinline__ uint32_t sm_addr(const void* p) {
    return (uint32_t)__cvta_generic_to_shared(p);
}
__device__ __forceinline__ void ldsm4(uint32_t a, uint32_t* r) {
    asm volatile("ldmatrix.sync.aligned.m8n8.x4.shared.b16 {%0,%1,%2,%3}, [%4];"
                 : "=r"(r[0]), "=r"(r[1]), "=r"(r[2]), "=r"(r[3]) : "r"(a));
}
__device__ __forceinline__ void ldsm4t(uint32_t a, uint32_t* r) {
    asm volatile("ldmatrix.sync.aligned.m8n8.x4.trans.shared.b16 {%0,%1,%2,%3}, [%4];"
                 : "=r"(r[0]), "=r"(r[1]), "=r"(r[2]), "=r"(r[3]) : "r"(a));
}
__device__ __forceinline__ void mma16816(float* d, const uint32_t* a, uint32_t b0, uint32_t b1) {
    asm volatile("mma.sync.aligned.m16n8k16.row.col.f32.bf16.bf16.f32 "
                 "{%0,%1,%2,%3}, {%4,%5,%6,%7}, {%8,%9}, {%0,%1,%2,%3};"
                 : "+f"(d[0]), "+f"(d[1]), "+f"(d[2]), "+f"(d[3])
                 : "r"(a[0]), "r"(a[1]), "r"(a[2]), "r"(a[3]), "r"(b0), "r"(b1));
}
__device__ __forceinline__ void split4(float4 v, __nv_bfloat16* hi, __nv_bfloat16* lo) {
    float f[4] = {v.x, v.y, v.z, v.w};
    __nv_bfloat162 h01, h23, l01, l23;
    __nv_bfloat16 h0 = __float2bfloat16_rn(f[0]);
    __nv_bfloat16 h1 = __float2bfloat16_rn(f[1]);
    __nv_bfloat16 h2 = __float2bfloat16_rn(f[2]);
    __nv_bfloat16 h3 = __float2bfloat16_rn(f[3]);
    h01.x = h0; h01.y = h1; h23.x = h2; h23.y = h3;
    l01.x = __float2bfloat16_rn(f[0] - __bfloat162float(h0));
    l01.y = __float2bfloat16_rn(f[1] - __bfloat162float(h1));
    l23.x = __float2bfloat16_rn(f[2] - __bfloat162float(h2));
    l23.y = __float2bfloat16_rn(f[3] - __bfloat162float(h3));
    *reinterpret_cast<__nv_bfloat162*>(hi)     = h01;
    *reinterpret_cast<__nv_bfloat162*>(hi + 2) = h23;
    *reinterpret_cast<__nv_bfloat162*>(lo)     = l01;
    *reinterpret_cast<__nv_bfloat162*>(lo + 2) = l23;
}

__device__ __forceinline__ void gemm_loop(uint32_t aHi0, uint32_t aLo0,
                                          uint32_t bHi, uint32_t bLo,
                                          float (&acc)[2][16][4]) {
    const uint32_t CH = 16 * LDS * 2;
    uint32_t ah[2][2][4], al[2][2][4];
    ldsm4(aHi0,      ah[0][0]);
    ldsm4(aLo0,      al[0][0]);
    ldsm4(aHi0 + CH, ah[0][1]);
    ldsm4(aLo0 + CH, al[0][1]);
#pragma unroll
    for (int ks = 0; ks < 8; ks++) {
        const int cab = ks & 1, nab = cab ^ 1;
        if (ks < 7) {
            ldsm4(aHi0 + (ks + 1) * 32,      ah[nab][0]);
            ldsm4(aLo0 + (ks + 1) * 32,      al[nab][0]);
            ldsm4(aHi0 + CH + (ks + 1) * 32, ah[nab][1]);
            ldsm4(aLo0 + CH + (ks + 1) * 32, al[nab][1]);
        }
        uint32_t bBaseH = bHi + (uint32_t)(ks * 16 * LDS) * 2u;
        uint32_t bBaseL = bLo + (uint32_t)(ks * 16 * LDS) * 2u;
        uint32_t bh[2][4], bl[2][4];
        ldsm4t(bBaseH, bh[0]);
        ldsm4t(bBaseL, bl[0]);
#pragma unroll
        for (int np = 0; np < 8; np++) {
            const int cur = np & 1, nxt = cur ^ 1;
            if (np < 7) {
                ldsm4t(bBaseH + (np + 1) * 32, bh[nxt]);
                ldsm4t(bBaseL + (np + 1) * 32, bl[nxt]);
            }
#pragma unroll
            for (int c = 0; c < 2; c++) {
                mma16816(acc[c][np * 2],     ah[cab][c], bh[cur][0], bh[cur][1]);
                mma16816(acc[c][np * 2 + 1], ah[cab][c], bh[cur][2], bh[cur][3]);
                mma16816(acc[c][np * 2],     ah[cab][c], bl[cur][0], bl[cur][1]);
                mma16816(acc[c][np * 2 + 1], ah[cab][c], bl[cur][2], bl[cur][3]);
                mma16816(acc[c][np * 2],     al[cab][c], bh[cur][0], bh[cur][1]);
                mma16816(acc[c][np * 2 + 1], al[cab][c], bh[cur][2], bh[cur][3]);
            }
        }
    }
}

#define MT 256
#define AB_BYTES ((2 * MT + 2 * 128) * LDS * 2)
#define G1_SMEM (AB_BYTES + 256 * 4 + 256 * 4)

// pool1[seg] += att[v] * relu(X[v]@W1)   (layer-1 GEMM + in-tile segmented reduce)
__global__ void __launch_bounds__(256, 1) k_gemm1(const float* __restrict__ X,
                                                  const float* __restrict__ W1,
                                                  int V) {
    extern __shared__ unsigned char smraw[];
    __nv_bfloat16* sAhi = (__nv_bfloat16*)smraw;
    __nv_bfloat16* sAlo = sAhi + (size_t)MT * LDS;
    __nv_bfloat16* sBhi = sAhi + (size_t)2 * MT * LDS;
    __nv_bfloat16* sBlo = sBhi + (size_t)128 * LDS;
    float* satt = (float*)(smraw + AB_BYTES);
    int*   sdid = (int*)(smraw + AB_BYTES + 256 * 4);
    float* smemF = (float*)smraw;     // epilogue alias

    int tid = threadIdx.x;
    int m0 = blockIdx.x * MT;

    {
        long gm = m0 + tid;
        bool ok = gm < V;
        satt[tid] = ok ? g_att[gm] : 0.f;
        sdid[tid] = g_didx[ok ? gm : (V - 1)];
    }

    for (int idx = tid; idx < MT * 32; idx += 256) {
        int r = idx >> 5, c4 = idx & 31;
        float4 v = (m0 + r < V) ? ((const float4*)X)[(size_t)(m0 + r) * 32 + c4]
                                : make_float4(0.f, 0.f, 0.f, 0.f);
        split4(v, sAhi + r * LDS + c4 * 4, sAlo + r * LDS + c4 * 4);
    }
    for (int idx = tid; idx < 128 * 32; idx += 256) {
        int r = idx >> 5, c4 = idx & 31;
        float4 v = ((const float4*)W1)[idx];
        split4(v, sBhi + r * LDS + c4 * 4, sBlo + r * LDS + c4 * 4);
    }
    __syncthreads();

    int w = tid >> 5, lane = tid & 31;
    int lr = lane & 15, lc = (lane >> 4) * 8;
    uint32_t aHi = sm_addr(sAhi + (w * 32 + lr) * LDS + lc);
    uint32_t aLo = sm_addr(sAlo + (w * 32 + lr) * LDS + lc);
    uint32_t bHi = sm_addr(sBhi + lr * LDS + lc);
    uint32_t bLo = sm_addr(sBlo + lr * LDS + lc);

    float acc[2][16][4];
#pragma unroll
    for (int c = 0; c < 2; c++)
#pragma unroll
        for (int t = 0; t < 16; t++)
#pragma unroll
            for (int i = 0; i < 4; i++) acc[c][t][i] = 0.f;

    gemm_loop(aHi, aLo, bHi, bLo, acc);
    __syncthreads();   // all warps done reading A/B -> safe to alias smemF

    int grp = lane >> 2, tq = lane & 3;
#pragma unroll
    for (int c = 0; c < 2; c++)
#pragma unroll
    for (int t = 0; t < 16; t++) {
        int col = t * 8 + tq * 2;
        int r0 = w * 32 + c * 16 + grp, r1 = r0 + 8;
        float a0 = satt[r0], a1 = satt[r1];
        smemF[r0 * 132 + col]     = fmaxf(acc[c][t][0], 0.f) * a0;
        smemF[r0 * 132 + col + 1] = fmaxf(acc[c][t][1], 0.f) * a0;
        smemF[r1 * 132 + col]     = fmaxf(acc[c][t][2], 0.f) * a1;
        smemF[r1 * 132 + col + 1] = fmaxf(acc[c][t][3], 0.f) * a1;
    }
    __syncthreads();

    // segmented reduction: thread (half, ch) scans 128 rows, RED per segment run
    {
        int half = tid >> 7, ch = tid & 127;
        int r = half * 128, rend = r + 128;
        float run = smemF[r * 132 + ch];
        int cur = sdid[r];
        for (r = r + 1; r < rend; r++) {
            int sg = sdid[r];
            float v = smemF[r * 132 + ch];
            if (sg == cur) run += v;
            else {
                atomicAdd(&g_pool1[(size_t)cur * 128 + ch], run);
                cur = sg; run = v;
            }
        }
        atomicAdd(&g_pool1[(size_t)cur * 128 + ch], run);
    }
}

#define G2_SMEM AB_BYTES

// out[N,128] = pool1[N,128] @ W2   (small single-layer GEMM)
__global__ void __launch_bounds__(256, 1) k_gemm2(const float* __restrict__ W2,
                                                  float* __restrict__ out, int N) {
    extern __shared__ __nv_bfloat16 sm[];
    __nv_bfloat16* sAhi = sm;
    __nv_bfloat16* sAlo = sm + (size_t)MT * LDS;
    __nv_bfloat16* sBhi = sm + (size_t)2 * MT * LDS;
    __nv_bfloat16* sBlo = sBhi + (size_t)128 * LDS;

    int tid = threadIdx.x;
    int m0 = blockIdx.x * MT;

    for (int idx = tid; idx < MT * 32; idx += 256) {
        int r = idx >> 5, c4 = idx & 31;
        float4 v = (m0 + r < N) ? ((const float4*)g_pool1)[(size_t)(m0 + r) * 32 + c4]
                                : make_float4(0.f, 0.f, 0.f, 0.f);
        split4(v, sAhi + r * LDS + c4 * 4, sAlo + r * LDS + c4 * 4);
    }
    for (int idx = tid; idx < 128 * 32; idx += 256) {
        int r = idx >> 5, c4 = idx & 31;
        float4 v = ((const float4*)W2)[idx];
        split4(v, sBhi + r * LDS + c4 * 4, sBlo + r * LDS + c4 * 4);
    }
    __syncthreads();

    int w = tid >> 5, lane = tid & 31;
    int lr = lane & 15, lc = (lane >> 4) * 8;
    uint32_t aHi = sm_addr(sAhi + (w * 32 + lr) * LDS + lc);
    uint32_t aLo = sm_addr(sAlo + (w * 32 + lr) * LDS + lc);
    uint32_t bHi = sm_addr(sBhi + lr * LDS + lc);
    uint32_t bLo = sm_addr(sBlo + lr * LDS + lc);

    float acc[2][16][4];
#pragma unroll
    for (int c = 0; c < 2; c++)
#pragma unroll
        for (int t = 0; t < 16; t++)
#pragma unroll
            for (int i = 0; i < 4; i++) acc[c][t][i] = 0.f;

    gemm_loop(aHi, aLo, bHi, bLo, acc);

    int grp = lane >> 2, tq = lane & 3;
#pragma unroll
    for (int c = 0; c < 2; c++)
#pragma unroll
    for (int t = 0; t < 16; t++) {
        int col = t * 8 + tq * 2;
        int gm0 = m0 + w * 32 + c * 16 + grp;
        int gm1 = gm0 + 8;
        if (gm0 < N) {
            float2 o; o.x = acc[c][t][0]; o.y = acc[c][t][1];
            *reinterpret_cast<float2*>(&out[(size_t)gm0 * 128 + col]) = o;
        }
        if (gm1 < N) {
            float2 o; o.x = acc[c][t][2]; o.y = acc[c][t][3];
            *reinterpret_cast<float2*>(&out[(size_t)gm1 * 128 + col]) = o;
        }
    }
}

// ---------------- launch ----------------
extern "C" void kernel_launch(void* const* d_in, const int* in_sizes, int n_in,
                              void* d_out, int out_size) {
    const float* x_main  = (const float*)d_in[0];
    const float* x_mod   = (const float*)d_in[1];
    const float* x_map   = (const float*)d_in[2];
    const int*   csr     = (const int*)  d_in[3];
    const float* W_main1 = (const float*)d_in[4];
    const float* W_main2 = (const float*)d_in[5];
    const float* W_map1  = (const float*)d_in[6];
    const float* W_map2  = (const float*)d_in[7];
    const float* W_mod1  = (const float*)d_in[8];
    const float* W_mod2  = (const float*)d_in[9];
    const float* WQ      = (const float*)d_in[10];
    const float* bQ      = (const float*)d_in[11];
    const float* WK      = (const float*)d_in[12];
    const float* bK      = (const float*)d_in[13];
    const float* gw      = (const float*)d_in[14];
    const float* gb      = (const float*)d_in[15];

    int N = in_sizes[3] - 1;
    int V = in_sizes[2] / 16;

    float* out = (float*)d_out;
    float* seen = nullptr;
    int writeSeen = 0;
    long long written = (long long)N * 128;
    if ((long long)out_size >= (long long)N * 128 + N) {
        seen = out + (size_t)N * 128;
        writeSeen = 1;
        written += N;
    }

    k_zero_pool1<<<(N * 128 + 255) / 256, 256>>>(N * 128);
    k_zero_ctx<<<(N * 32 + 255) / 256, 256>>>(N * 32);
    k_didx<<<(V + 255) / 256, 256>>>(csr, N, V);
    k_q<<<(N + 31) / 32, 256>>>(x_main, W_main1, W_main2, WQ, bQ, N);
    k_h<<<(V + 63) / 64, 256>>>(x_map, W_map1, V);
    k_ctx2<<<(N + 7) / 8, 256>>>(W_map2, N);
    k_comp<<<(V + 63) / 64, 256>>>(W_map2, WK, bK, V);
    k_att<<<N, 128>>>(csr, gw, gb, seen, writeSeen);

    cudaFuncSetAttribute(k_gemm1, cudaFuncAttributeMaxDynamicSharedMemorySize, G1_SMEM);
    k_gemm1<<<(V + MT - 1) / MT, 256, G1_SMEM>>>(x_mod, W_mod1, V);

    cudaFuncSetAttribute(k_gemm2, cudaFuncAttributeMaxDynamicSharedMemorySize, G2_SMEM);
    k_gemm2<<<(N + MT - 1) / MT, 256, G2_SMEM>>>(W_mod2, out, N);

    long long tail = (long long)out_size - written;
    if (tail > 0) {
        k_tail_zero<<<(int)((tail + 255) / 256), 256>>>(out + written, (int)tail);
    }
}

// round 16
// speedup vs baseline: 1.3402x; 1.0554x over previous
#include <cuda_runtime.h>
#include <cuda_bf16.h>
#include <cstdint>
#include <math.h>

#define NPTS  50000
#define NVIEW 500000
#define LDS   136   // 128 + 8 bf16 padding -> conflict-free ldmatrix

// ---------------- scratch (device globals; no allocations) ----------------
__device__ int   g_didx[NVIEW];
__device__ float g_q[NPTS * 8];
__device__ float g_h[(size_t)NVIEW * 32];
__device__ float g_ctx[NPTS * 32];
__device__ float g_c2[NPTS * 32];
__device__ float g_comp[NVIEW];
__device__ float g_att[NVIEW];             // softmax * gate, per view
__device__ float g_pool1[(size_t)NPTS * 128]; // segment-pooled relu(x@W1)

// ---------------- small utility kernels ----------------
__global__ void k_zero_scratch(int nCtx, int nPool) {
    int i = blockIdx.x * blockDim.x + threadIdx.x;
    if (i < nCtx) g_ctx[i] = 0.0f;
    else if (i < nCtx + nPool) g_pool1[i - nCtx] = 0.0f;
}
__global__ void k_tail_zero(float* p, int n) {
    int i = blockIdx.x * blockDim.x + threadIdx.x;
    if (i < n) p[i] = 0.0f;
}

__global__ void k_didx(const int* __restrict__ csr, int N, int V) {
    int v = blockIdx.x * blockDim.x + threadIdx.x;
    if (v >= V) return;
    int lo = 0, hi = N - 1;
    while (lo < hi) {
        int mid = (lo + hi) >> 1;
        if (csr[mid + 1] <= v) lo = mid + 1; else hi = mid;
    }
    g_didx[v] = lo;
}

// ---------------- per-point queries (4 points/warp, split accumulators) ----------------
__global__ void __launch_bounds__(256) k_q(const float* __restrict__ xm,
                                           const float* __restrict__ W1,
                                           const float* __restrict__ W2,
                                           const float* __restrict__ WQ,
                                           const float* __restrict__ bQ, int N) {
    __shared__ float sW1[64 * 32];
    __shared__ float sW2[32 * 32];
    __shared__ float sWQ[32 * 8];
    __shared__ __align__(16) float sxq[8][260];
    __shared__ float s1[8][36];
    __shared__ float s2[8][36];
    int tid = threadIdx.x;
    for (int i = tid; i < 64 * 32; i += 256) sW1[i] = W1[i];
    for (int i = tid; i < 32 * 32; i += 256) sW2[i] = W2[i];
    for (int i = tid; i < 32 * 8;  i += 256) sWQ[i] = WQ[i];
    __syncthreads();
    int w = tid >> 5, j = tid & 31;
    int p0 = (blockIdx.x * 8 + w) * 4;
    if (p0 >= N) return;
    int np = N - p0; if (np > 4) np = 4;

    if (p0 + 3 < N) {
        const float4* src = (const float4*)(xm + (size_t)p0 * 64);
        float4 t0 = src[j], t1 = src[j + 32];
        *(float4*)&sxq[w][j * 4]       = t0;
        *(float4*)&sxq[w][128 + j * 4] = t1;
    } else {
        for (int idx = j; idx < np * 64; idx += 32)
            sxq[w][idx] = xm[(size_t)p0 * 64 + idx];
    }
    __syncwarp();

    for (int u = 0; u < np; u++) {
        float a0 = 0.f, a1 = 0.f, a2 = 0.f, a3 = 0.f;
#pragma unroll
        for (int i = 0; i < 64; i += 4) {
            a0 += sxq[w][u * 64 + i]     * sW1[i * 32 + j];
            a1 += sxq[w][u * 64 + i + 1] * sW1[(i + 1) * 32 + j];
            a2 += sxq[w][u * 64 + i + 2] * sW1[(i + 2) * 32 + j];
            a3 += sxq[w][u * 64 + i + 3] * sW1[(i + 3) * 32 + j];
        }
        s1[w][j] = fmaxf((a0 + a1) + (a2 + a3), 0.f);
        __syncwarp();
        a0 = 0.f; a1 = 0.f;
#pragma unroll
        for (int i = 0; i < 32; i += 2) {
            a0 += s1[w][i]     * sW2[i * 32 + j];
            a1 += s1[w][i + 1] * sW2[(i + 1) * 32 + j];
        }
        s2[w][j] = a0 + a1;
        __syncwarp();
        if (j < 8) {
            a0 = bQ[j]; a1 = 0.f;
#pragma unroll
            for (int i = 0; i < 32; i += 2) {
                a0 += s2[w][i]     * sWQ[i * 8 + j];
                a1 += s2[w][i + 1] * sWQ[(i + 1) * 8 + j];
            }
            g_q[(size_t)(p0 + u) * 8 + j] = a0 + a1;
        }
        __syncwarp();
    }
}

// ------ per-view h = relu(x_map@W_map1); 8 views/warp, aggregated seg-max ------
__global__ void __launch_bounds__(256) k_h(const float* __restrict__ xmap,
                                           const float* __restrict__ W1, int V) {
    __shared__ float sW[16 * 32];
    __shared__ __align__(16) float sx[8][68];
    int tid = threadIdx.x;
    for (int i = tid; i < 16 * 32; i += 256) sW[i] = W1[i];
    __syncthreads();
    int w = tid >> 5, j = tid & 31;
    int vbase = (blockIdx.x * 8 + w) * 8;

    for (int pass = 0; pass < 2; pass++) {
        int v0 = vbase + pass * 4;
        if (v0 >= V) break;
        int nv = V - v0; if (nv > 4) nv = 4;

        if (v0 + 3 < V) {
            if (j < 16) {
                float4 t = ((const float4*)xmap)[(size_t)v0 * 4 + j];
                float* d = &sx[w][j * 4];
                d[0] = t.x; d[1] = t.y; d[2] = t.z; d[3] = t.w;
            }
        } else {
            for (int idx = j; idx < nv * 16; idx += 32)
                sx[w][idx] = xmap[(size_t)v0 * 16 + idx];
        }
        __syncwarp();

        float h[4];
        int seg[4];
#pragma unroll
        for (int u = 0; u < 4; u++) {
            if (u < nv) {
                float a0 = 0.f, a1 = 0.f;
#pragma unroll
                for (int i = 0; i < 16; i += 2) {
                    a0 += sx[w][u * 16 + i]     * sW[i * 32 + j];
                    a1 += sx[w][u * 16 + i + 1] * sW[(i + 1) * 32 + j];
                }
                h[u] = fmaxf(a0 + a1, 0.f);
                g_h[(size_t)(v0 + u) * 32 + j] = h[u];
                seg[u] = g_didx[v0 + u];
            }
        }
        float m = h[0]; int cs = seg[0];
#pragma unroll
        for (int u = 1; u < 4; u++) {
            if (u < nv) {
                if (seg[u] == cs) m = fmaxf(m, h[u]);
                else {
                    atomicMax((int*)&g_ctx[cs * 32 + j], __float_as_int(m));
                    cs = seg[u]; m = h[u];
                }
            }
        }
        atomicMax((int*)&g_ctx[cs * 32 + j], __float_as_int(m));
        __syncwarp();
    }
}

// -------- per-segment: c2 = ctx @ W2[32:64] --------
__global__ void __launch_bounds__(256) k_ctx2(const float* __restrict__ W2, int N) {
    __shared__ float sW[32 * 32];
    __shared__ float sx[8][32];
    int tid = threadIdx.x;
    for (int i = tid; i < 32 * 32; i += 256) sW[i] = W2[32 * 32 + i];
    __syncthreads();
    int w = tid >> 5, j = tid & 31;
    int p = blockIdx.x * 8 + w;
    if (p >= N) return;
    sx[w][j] = g_ctx[p * 32 + j];
    __syncwarp();
    float a0 = 0.f, a1 = 0.f;
#pragma unroll
    for (int i = 0; i < 32; i += 2) {
        a0 += sx[w][i]     * sW[i * 32 + j];
        a1 += sx[w][i + 1] * sW[(i + 1) * 32 + j];
    }
    g_c2[p * 32 + j] = a0 + a1;
}

// ---------------- per-view comp (8 views/warp in 2 passes, split accumulators) ----------------
__global__ void __launch_bounds__(256) k_comp(const float* __restrict__ W2,
                                              const float* __restrict__ WK,
                                              const float* __restrict__ bK, int V) {
    __shared__ float sW[32 * 32];
    __shared__ float sWK[32 * 8];
    __shared__ __align__(16) float cat[8][132];
    __shared__ float kv[8][132];
    int tid = threadIdx.x;
    for (int i = tid; i < 32 * 32; i += 256) sW[i] = W2[i];
    for (int i = tid; i < 32 * 8;  i += 256) sWK[i] = WK[i];
    __syncthreads();
    int w = tid >> 5, j = tid & 31;
    int vbase = (blockIdx.x * 8 + w) * 8;

    for (int pass = 0; pass < 2; pass++) {
        int v0 = vbase + pass * 4;
        if (v0 >= V) break;
        int nv = V - v0; if (nv > 4) nv = 4;

        if (v0 + 3 < V) {
            float4 t = ((const float4*)(g_h + (size_t)v0 * 32))[j];
            float* d = &cat[w][j * 4];
            d[0] = t.x; d[1] = t.y; d[2] = t.z; d[3] = t.w;
        } else {
            for (int idx = j; idx < nv * 32; idx += 32)
                cat[w][idx] = g_h[(size_t)v0 * 32 + idx];
        }
        __syncwarp();

#pragma unroll
        for (int u = 0; u < 4; u++) {
            if (u < nv) {
                int sg = g_didx[v0 + u];
                float a0 = g_c2[sg * 32 + j], a1 = 0.f;
#pragma unroll
                for (int i = 0; i < 32; i += 2) {
                    a0 += cat[w][u * 32 + i]     * sW[i * 32 + j];
                    a1 += cat[w][u * 32 + i + 1] * sW[(i + 1) * 32 + j];
                }
                kv[w][u * 32 + j] = fmaxf(a0 + a1, 0.f);
            }
        }
        __syncwarp();

        int u = j >> 3, jq = j & 7;
        float c = 0.f;
        if (u < nv) {
            int segu = g_didx[v0 + u];
            float a0 = bK[jq], a1 = 0.f;
#pragma unroll
            for (int i = 0; i < 32; i += 2) {
                a0 += kv[w][u * 32 + i]     * sWK[i * 8 + jq];
                a1 += kv[w][u * 32 + i + 1] * sWK[(i + 1) * 8 + jq];
            }
            c = (a0 + a1) * g_q[(size_t)segu * 8 + jq];
        }
        c += __shfl_down_sync(0xffffffff, c, 4, 8);
        c += __shfl_down_sync(0xffffffff, c, 2, 8);
        c += __shfl_down_sync(0xffffffff, c, 1, 8);
        if (jq == 0 && u < nv) g_comp[v0 + u] = c * 0.35355339059327373f;
        __syncwarp();
    }
}

// ------- per-segment softmax + gate -> g_att (warp per segment, 8/block) -------
__global__ void __launch_bounds__(256) k_att(const int* __restrict__ csr,
                                             const float* __restrict__ gw,
                                             const float* __restrict__ gb,
                                             float* __restrict__ seen,
                                             int writeSeen, int N) {
    int w = threadIdx.x >> 5, lane = threadIdx.x & 31;
    int n = blockIdx.x * 8 + w;
    if (n >= N) return;
    int s = csr[n], e = csr[n + 1];
    if (e <= s) {
        if (writeSeen && lane == 0) seen[n] = 0.f;
        return;
    }
    float m = -INFINITY;
    for (int v = s + lane; v < e; v += 32) m = fmaxf(m, g_comp[v]);
#pragma unroll
    for (int off = 16; off > 0; off >>= 1)
        m = fmaxf(m, __shfl_xor_sync(0xffffffff, m, off));
    float sum = 0.f;
    for (int v = s + lane; v < e; v += 32) sum += expf(g_comp[v] - m);
#pragma unroll
    for (int off = 16; off > 0; off >>= 1)
        sum += __shfl_xor_sync(0xffffffff, sum, off);
    float gate = tanhf(fmaxf(gw[0] * m + gb[0], 0.f));
    float winv = gate / (sum + 1e-12f);
    for (int v = s + lane; v < e; v += 32)
        g_att[v] = expf(g_comp[v] - m) * winv;
    if (writeSeen && lane == 0) seen[n] = 1.f;
}

// ---------------- tensor-core GEMM machinery (split-bf16, 3-MMA, M=256) ----------------
__device__ __forceinline__ uint32_t sm_addr(const void* p) {
    return (uint32_t)__cvta_generic_to_shared(p);
}
__device__ __forceinline__ void ldsm4(uint32_t a, uint32_t* r) {
    asm volatile("ldmatrix.sync.aligned.m8n8.x4.shared.b16 {%0,%1,%2,%3}, [%4];"
                 : "=r"(r[0]), "=r"(r[1]), "=r"(r[2]), "=r"(r[3]) : "r"(a));
}
__device__ __forceinline__ void ldsm4t(uint32_t a, uint32_t* r) {
    asm volatile("ldmatrix.sync.aligned.m8n8.x4.trans.shared.b16 {%0,%1,%2,%3}, [%4];"
                 : "=r"(r[0]), "=r"(r[1]), "=r"(r[2]), "=r"(r[3]) : "r"(a));
}
__device__ __forceinline__ void mma16816(float* d, const uint32_t* a, uint32_t b0, uint32_t b1) {
    asm volatile("mma.sync.aligned.m16n8k16.row.col.f32.bf16.bf16.f32 "
                 "{%0,%1,%2,%3}, {%4,%5,%6,%7}, {%8,%9}, {%0,%1,%2,%3};"
                 : "+f"(d[0]), "+f"(d[1]), "+f"(d[2]), "+f"(d[3])
                 : "r"(a[0]), "r"(a[1]), "r"(a[2]), "r"(a[3]), "r"(b0), "r"(b1));
}
__device__ __forceinline__ void split4(float4 v, __nv_bfloat16* hi, __nv_bfloat16* lo) {
    float f[4] = {v.x, v.y, v.z, v.w};
    __nv_bfloat162 h01, h23, l01, l23;
    __nv_bfloat16 h0 = __float2bfloat16_rn(f[0]);
    __nv_bfloat16 h1 = __float2bfloat16_rn(f[1]);
    __nv_bfloat16 h2 = __float2bfloat16_rn(f[2]);
    __nv_bfloat16 h3 = __float2bfloat16_rn(f[3]);
    h01.x = h0; h01.y = h1; h23.x = h2; h23.y = h3;
    l01.x = __float2bfloat16_rn(f[0] - __bfloat162float(h0));
    l01.y = __float2bfloat16_rn(f[1] - __bfloat162float(h1));
    l23.x = __float2bfloat16_rn(f[2] - __bfloat162float(h2));
    l23.y = __float2bfloat16_rn(f[3] - __bfloat162float(h3));
    *reinterpret_cast<__nv_bfloat162*>(hi)     = h01;
    *reinterpret_cast<__nv_bfloat162*>(hi + 2) = h23;
    *reinterpret_cast<__nv_bfloat162*>(lo)     = l01;
    *reinterpret_cast<__nv_bfloat162*>(lo + 2) = l23;
}

__device__ __forceinline__ void gemm_loop(uint32_t aHi0, uint32_t aLo0,
                                          uint32_t bHi, uint32_t bLo,
                                          float (&acc)[2][16][4]) {
    const uint32_t CH = 16 * LDS * 2;
    uint32_t ah[2][2][4], al[2][2][4];
    ldsm4(aHi0,      ah[0][0]);
    ldsm4(aLo0,      al[0][0]);
    ldsm4(aHi0 + CH, ah[0][1]);
    ldsm4(aLo0 + CH, al[0][1]);
#pragma unroll
    for (int ks = 0; ks < 8; ks++) {
        const int cab = ks & 1, nab = cab ^ 1;
        if (ks < 7) {
            ldsm4(aHi0 + (ks + 1) * 32,      ah[nab][0]);
            ldsm4(aLo0 + (ks + 1) * 32,      al[nab][0]);
            ldsm4(aHi0 + CH + (ks + 1) * 32, ah[nab][1]);
            ldsm4(aLo0 + CH + (ks + 1) * 32, al[nab][1]);
        }
        uint32_t bBaseH = bHi + (uint32_t)(ks * 16 * LDS) * 2u;
        uint32_t bBaseL = bLo + (uint32_t)(ks * 16 * LDS) * 2u;
        uint32_t bh[2][4], bl[2][4];
        ldsm4t(bBaseH, bh[0]);
        ldsm4t(bBaseL, bl[0]);
#pragma unroll
        for (int np = 0; np < 8; np++) {
            const int cur = np & 1, nxt = cur ^ 1;
            if (np < 7) {
                ldsm4t(bBaseH + (np + 1) * 32, bh[nxt]);
                ldsm4t(bBaseL + (np + 1) * 32, bl[nxt]);
            }
#pragma unroll
            for (int c = 0; c < 2; c++) {
                mma16816(acc[c][np * 2],     ah[cab][c], bh[cur][0], bh[cur][1]);
                mma16816(acc[c][np * 2 + 1], ah[cab][c], bh[cur][2], bh[cur][3]);
                mma16816(acc[c][np * 2],     ah[cab][c], bl[cur][0], bl[cur][1]);
                mma16816(acc[c][np * 2 + 1], ah[cab][c], bl[cur][2], bl[cur][3]);
                mma16816(acc[c][np * 2],     al[cab][c], bh[cur][0], bh[cur][1]);
                mma16816(acc[c][np * 2 + 1], al[cab][c], bh[cur][2], bh[cur][3]);
            }
        }
    }
}

#define MT 256
#define AB_BYTES ((2 * MT + 2 * 128) * LDS * 2)
#define G1_SMEM (AB_BYTES + 256 * 4 + 256 * 4)

// pool1[seg] += att[v] * relu(X[v]@W1)   (layer-1 GEMM + in-tile segmented reduce)
__global__ void __launch_bounds__(256, 1) k_gemm1(const float* __restrict__ X,
                                                  const float* __restrict__ W1,
                                                  int V) {
    extern __shared__ unsigned char smraw[];
    __nv_bfloat16* sAhi = (__nv_bfloat16*)smraw;
    __nv_bfloat16* sAlo = sAhi + (size_t)MT * LDS;
    __nv_bfloat16* sBhi = sAhi + (size_t)2 * MT * LDS;
    __nv_bfloat16* sBlo = sBhi + (size_t)128 * LDS;
    float* satt = (float*)(smraw + AB_BYTES);
    int*   sdid = (int*)(smraw + AB_BYTES + 256 * 4);
    float* smemF = (float*)smraw;     // epilogue alias

    int tid = threadIdx.x;
    int m0 = blockIdx.x * MT;

    {
        long gm = m0 + tid;
        bool ok = gm < V;
        satt[tid] = ok ? g_att[gm] : 0.f;
        sdid[tid] = g_didx[ok ? gm : (V - 1)];
    }

    for (int idx = tid; idx < MT * 32; idx += 256) {
        int r = idx >> 5, c4 = idx & 31;
        float4 v = (m0 + r < V) ? ((const float4*)X)[(size_t)(m0 + r) * 32 + c4]
                                : make_float4(0.f, 0.f, 0.f, 0.f);
        split4(v, sAhi + r * LDS + c4 * 4, sAlo + r * LDS + c4 * 4);
    }
    for (int idx = tid; idx < 128 * 32; idx += 256) {
        int r = idx >> 5, c4 = idx & 31;
        float4 v = ((const float4*)W1)[idx];
        split4(v, sBhi + r * LDS + c4 * 4, sBlo + r * LDS + c4 * 4);
    }
    __syncthreads();

    int w = tid >> 5, lane = tid & 31;
    int lr = lane & 15, lc = (lane >> 4) * 8;
    uint32_t aHi = sm_addr(sAhi + (w * 32 + lr) * LDS + lc);
    uint32_t aLo = sm_addr(sAlo + (w * 32 + lr) * LDS + lc);
    uint32_t bHi = sm_addr(sBhi + lr * LDS + lc);
    uint32_t bLo = sm_addr(sBlo + lr * LDS + lc);

    float acc[2][16][4];
#pragma unroll
    for (int c = 0; c < 2; c++)
#pragma unroll
        for (int t = 0; t < 16; t++)
#pragma unroll
            for (int i = 0; i < 4; i++) acc[c][t][i] = 0.f;

    gemm_loop(aHi, aLo, bHi, bLo, acc);
    __syncthreads();   // all warps done reading A/B -> safe to alias smemF

    int grp = lane >> 2, tq = lane & 3;
#pragma unroll
    for (int c = 0; c < 2; c++)
#pragma unroll
    for (int t = 0; t < 16; t++) {
        int col = t * 8 + tq * 2;
        int r0 = w * 32 + c * 16 + grp, r1 = r0 + 8;
        float a0 = satt[r0], a1 = satt[r1];
        smemF[r0 * 132 + col]     = fmaxf(acc[c][t][0], 0.f) * a0;
        smemF[r0 * 132 + col + 1] = fmaxf(acc[c][t][1], 0.f) * a0;
        smemF[r1 * 132 + col]     = fmaxf(acc[c][t][2], 0.f) * a1;
        smemF[r1 * 132 + col + 1] = fmaxf(acc[c][t][3], 0.f) * a1;
    }
    __syncthreads();

    // segmented reduction: thread (half, ch) scans 128 rows, RED per segment run
    {
        int half = tid >> 7, ch = tid & 127;
        int r = half * 128, rend = r + 128;
        float run = smemF[r * 132 + ch];
        int cur = sdid[r];
        for (r = r + 1; r < rend; r++) {
            int sg = sdid[r];
            float v = smemF[r * 132 + ch];
            if (sg == cur) run += v;
            else {
                atomicAdd(&g_pool1[(size_t)cur * 128 + ch], run);
                cur = sg; run = v;
            }
        }
        atomicAdd(&g_pool1[(size_t)cur * 128 + ch], run);
    }
}

#define G2_SMEM AB_BYTES

// out[N,128] = pool1[N,128] @ W2   (small single-layer GEMM)
__global__ void __launch_bounds__(256, 1) k_gemm2(const float* __restrict__ W2,
                                                  float* __restrict__ out, int N) {
    extern __shared__ __nv_bfloat16 sm[];
    __nv_bfloat16* sAhi = sm;
    __nv_bfloat16* sAlo = sm + (size_t)MT * LDS;
    __nv_bfloat16* sBhi = sm + (size_t)2 * MT * LDS;
    __nv_bfloat16* sBlo = sBhi + (size_t)128 * LDS;

    int tid = threadIdx.x;
    int m0 = blockIdx.x * MT;

    for (int idx = tid; idx < MT * 32; idx += 256) {
        int r = idx >> 5, c4 = idx & 31;
        float4 v = (m0 + r < N) ? ((const float4*)g_pool1)[(size_t)(m0 + r) * 32 + c4]
                                : make_float4(0.f, 0.f, 0.f, 0.f);
        split4(v, sAhi + r * LDS + c4 * 4, sAlo + r * LDS + c4 * 4);
    }
    for (int idx = tid; idx < 128 * 32; idx += 256) {
        int r = idx >> 5, c4 = idx & 31;
        float4 v = ((const float4*)W2)[idx];
        split4(v, sBhi + r * LDS + c4 * 4, sBlo + r * LDS + c4 * 4);
    }
    __syncthreads();

    int w = tid >> 5, lane = tid & 31;
    int lr = lane & 15, lc = (lane >> 4) * 8;
    uint32_t aHi = sm_addr(sAhi + (w * 32 + lr) * LDS + lc);
    uint32_t aLo = sm_addr(sAlo + (w * 32 + lr) * LDS + lc);
    uint32_t bHi = sm_addr(sBhi + lr * LDS + lc);
    uint32_t bLo = sm_addr(sBlo + lr * LDS + lc);

    float acc[2][16][4];
#pragma unroll
    for (int c = 0; c < 2; c++)
#pragma unroll
        for (int t = 0; t < 16; t++)
#pragma unroll
            for (int i = 0; i < 4; i++) acc[c][t][i] = 0.f;

    gemm_loop(aHi, aLo, bHi, bLo, acc);

    int grp = lane >> 2, tq = lane & 3;
#pragma unroll
    for (int c = 0; c < 2; c++)
#pragma unroll
    for (int t = 0; t < 16; t++) {
        int col = t * 8 + tq * 2;
        int gm0 = m0 + w * 32 + c * 16 + grp;
        int gm1 = gm0 + 8;
        if (gm0 < N) {
            float2 o; o.x = acc[c][t][0]; o.y = acc[c][t][1];
            *reinterpret_cast<float2*>(&out[(size_t)gm0 * 128 + col]) = o;
        }
        if (gm1 < N) {
            float2 o; o.x = acc[c][t][2]; o.y = acc[c][t][3];
            *reinterpret_cast<float2*>(&out[(size_t)gm1 * 128 + col]) = o;
        }
    }
}

// ---------------- launch ----------------
extern "C" void kernel_launch(void* const* d_in, const int* in_sizes, int n_in,
                              void* d_out, int out_size) {
    const float* x_main  = (const float*)d_in[0];
    const float* x_mod   = (const float*)d_in[1];
    const float* x_map   = (const float*)d_in[2];
    const int*   csr     = (const int*)  d_in[3];
    const float* W_main1 = (const float*)d_in[4];
    const float* W_main2 = (const float*)d_in[5];
    const float* W_map1  = (const float*)d_in[6];
    const float* W_map2  = (const float*)d_in[7];
    const float* W_mod1  = (const float*)d_in[8];
    const float* W_mod2  = (const float*)d_in[9];
    const float* WQ      = (const float*)d_in[10];
    const float* bQ      = (const float*)d_in[11];
    const float* WK      = (const float*)d_in[12];
    const float* bK      = (const float*)d_in[13];
    const float* gw      = (const float*)d_in[14];
    const float* gb      = (const float*)d_in[15];

    int N = in_sizes[3] - 1;
    int V = in_sizes[2] / 16;

    float* out = (float*)d_out;
    float* seen = nullptr;
    int writeSeen = 0;
    long long written = (long long)N * 128;
    if ((long long)out_size >= (long long)N * 128 + N) {
        seen = out + (size_t)N * 128;
        writeSeen = 1;
        written += N;
    }

    k_zero_scratch<<<(N * 160 + 255) / 256, 256>>>(N * 32, N * 128);
    k_didx<<<(V + 255) / 256, 256>>>(csr, N, V);
    k_q<<<(N + 31) / 32, 256>>>(x_main, W_main1, W_main2, WQ, bQ, N);
    k_h<<<(V + 63) / 64, 256>>>(x_map, W_map1, V);
    k_ctx2<<<(N + 7) / 8, 256>>>(W_map2, N);
    k_comp<<<(V + 63) / 64, 256>>>(W_map2, WK, bK, V);
    k_att<<<(N + 7) / 8, 256>>>(csr, gw, gb, seen, writeSeen, N);

    cudaFuncSetAttribute(k_gemm1, cudaFuncAttributeMaxDynamicSharedMemorySize, G1_SMEM);
    k_gemm1<<<(V + MT - 1) / MT, 256, G1_SMEM>>>(x_mod, W_mod1, V);

    cudaFuncSetAttribute(k_gemm2, cudaFuncAttributeMaxDynamicSharedMemorySize, G2_SMEM);
    k_gemm2<<<(N + MT - 1) / MT, 256, G2_SMEM>>>(W_mod2, out, N);

    long long tail = (long long)out_size - written;
    if (tail > 0) {
        k_tail_zero<<<(int)((tail + 255) / 256), 256>>>(out + written, (int)tail);
    }
}

// round 17
// speedup vs baseline: 1.3869x; 1.0348x over previous
#include <cuda_runtime.h>
#include <cuda_bf16.h>
#include <cstdint>
#include <math.h>

#define NPTS  50000
#define NVIEW 500000
#define LDS   136   // 128 + 8 bf16 padding -> conflict-free ldmatrix

// ---------------- scratch (device globals; no allocations) ----------------
__device__ int   g_didx[NVIEW];
__device__ float g_q[NPTS * 8];
__device__ float g_h[(size_t)NVIEW * 32];
__device__ float g_ctx[NPTS * 32];
__device__ float g_c2[NPTS * 32];
__device__ float g_comp[NVIEW];
__device__ float g_att[NVIEW];             // softmax * gate, per view
__device__ float g_pool1[(size_t)NPTS * 128]; // segment-pooled relu(x@W1)

// ---------------- small utility kernels ----------------
__global__ void k_zero_scratch(int nCtx, int nPool) {
    int i = blockIdx.x * blockDim.x + threadIdx.x;
    if (i < nCtx) g_ctx[i] = 0.0f;
    else if (i < nCtx + nPool) g_pool1[i - nCtx] = 0.0f;
}
__global__ void k_tail_zero(float* p, int n) {
    int i = blockIdx.x * blockDim.x + threadIdx.x;
    if (i < n) p[i] = 0.0f;
}

__global__ void k_didx(const int* __restrict__ csr, int N, int V) {
    int v = blockIdx.x * blockDim.x + threadIdx.x;
    if (v >= V) return;
    int lo = 0, hi = N - 1;
    while (lo < hi) {
        int mid = (lo + hi) >> 1;
        if (csr[mid + 1] <= v) lo = mid + 1; else hi = mid;
    }
    g_didx[v] = lo;
}

// ------- per-point queries (4 points/warp, stages interleaved across points) -------
__global__ void __launch_bounds__(256) k_q(const float* __restrict__ xm,
                                           const float* __restrict__ W1,
                                           const float* __restrict__ W2,
                                           const float* __restrict__ WQ,
                                           const float* __restrict__ bQ, int N) {
    __shared__ float sW1[64 * 32];
    __shared__ float sW2[32 * 32];
    __shared__ float sWQ[32 * 8];
    __shared__ __align__(16) float sxq[8][260];
    __shared__ float s1[8][4][36];
    __shared__ float s2[8][4][36];
    int tid = threadIdx.x;
    for (int i = tid; i < 64 * 32; i += 256) sW1[i] = W1[i];
    for (int i = tid; i < 32 * 32; i += 256) sW2[i] = W2[i];
    for (int i = tid; i < 32 * 8;  i += 256) sWQ[i] = WQ[i];
    __syncthreads();
    int w = tid >> 5, j = tid & 31;
    int p0 = (blockIdx.x * 8 + w) * 4;
    if (p0 >= N) return;
    int np = N - p0; if (np > 4) np = 4;

    if (p0 + 3 < N) {
        const float4* src = (const float4*)(xm + (size_t)p0 * 64);
        float4 t0 = src[j], t1 = src[j + 32];
        *(float4*)&sxq[w][j * 4]       = t0;
        *(float4*)&sxq[w][128 + j * 4] = t1;
    } else {
        for (int idx = j; idx < 256; idx += 32) sxq[w][idx] = 0.f;
        __syncwarp();
        for (int idx = j; idx < np * 64; idx += 32)
            sxq[w][idx] = xm[(size_t)p0 * 64 + idx];
    }
    __syncwarp();

    // stage 1: all 4 points interleaved (weight LDS shared across points)
    {
        float a[4][2];
#pragma unroll
        for (int u = 0; u < 4; u++) { a[u][0] = 0.f; a[u][1] = 0.f; }
#pragma unroll
        for (int i = 0; i < 64; i += 2) {
            float w0 = sW1[i * 32 + j], w1 = sW1[(i + 1) * 32 + j];
#pragma unroll
            for (int u = 0; u < 4; u++) {
                a[u][0] += sxq[w][u * 64 + i]     * w0;
                a[u][1] += sxq[w][u * 64 + i + 1] * w1;
            }
        }
#pragma unroll
        for (int u = 0; u < 4; u++) s1[w][u][j] = fmaxf(a[u][0] + a[u][1], 0.f);
    }
    __syncwarp();
    // stage 2
    {
        float a[4][2];
#pragma unroll
        for (int u = 0; u < 4; u++) { a[u][0] = 0.f; a[u][1] = 0.f; }
#pragma unroll
        for (int i = 0; i < 32; i += 2) {
            float w0 = sW2[i * 32 + j], w1 = sW2[(i + 1) * 32 + j];
#pragma unroll
            for (int u = 0; u < 4; u++) {
                a[u][0] += s1[w][u][i]     * w0;
                a[u][1] += s1[w][u][i + 1] * w1;
            }
        }
#pragma unroll
        for (int u = 0; u < 4; u++) s2[w][u][j] = a[u][0] + a[u][1];
    }
    __syncwarp();
    // stage 3 (8 outputs)
    if (j < 8) {
        float a[4][2];
#pragma unroll
        for (int u = 0; u < 4; u++) { a[u][0] = bQ[j]; a[u][1] = 0.f; }
#pragma unroll
        for (int i = 0; i < 32; i += 2) {
            float w0 = sWQ[i * 8 + j], w1 = sWQ[(i + 1) * 8 + j];
#pragma unroll
            for (int u = 0; u < 4; u++) {
                a[u][0] += s2[w][u][i]     * w0;
                a[u][1] += s2[w][u][i + 1] * w1;
            }
        }
#pragma unroll
        for (int u = 0; u < 4; u++)
            if (u < np) g_q[(size_t)(p0 + u) * 8 + j] = a[u][0] + a[u][1];
    }
}

// ------ per-view h; 8 views/warp, register-cached weight column ------
__global__ void __launch_bounds__(256) k_h(const float* __restrict__ xmap,
                                           const float* __restrict__ W1, int V) {
    __shared__ float sW[16 * 32];
    __shared__ __align__(16) float sx[8][68];
    int tid = threadIdx.x;
    for (int i = tid; i < 16 * 32; i += 256) sW[i] = W1[i];
    __syncthreads();
    int w = tid >> 5, j = tid & 31;
    float wreg[16];
#pragma unroll
    for (int i = 0; i < 16; i++) wreg[i] = sW[i * 32 + j];
    int vbase = (blockIdx.x * 8 + w) * 8;

    for (int pass = 0; pass < 2; pass++) {
        int v0 = vbase + pass * 4;
        if (v0 >= V) break;
        int nv = V - v0; if (nv > 4) nv = 4;

        if (v0 + 3 < V) {
            if (j < 16) {
                float4 t = ((const float4*)xmap)[(size_t)v0 * 4 + j];
                float* d = &sx[w][j * 4];
                d[0] = t.x; d[1] = t.y; d[2] = t.z; d[3] = t.w;
            }
        } else {
            for (int idx = j; idx < nv * 16; idx += 32)
                sx[w][idx] = xmap[(size_t)v0 * 16 + idx];
        }
        __syncwarp();

        float h[4];
        int seg[4];
#pragma unroll
        for (int u = 0; u < 4; u++) {
            if (u < nv) {
                float a0 = 0.f, a1 = 0.f;
#pragma unroll
                for (int i = 0; i < 16; i += 2) {
                    a0 += sx[w][u * 16 + i]     * wreg[i];
                    a1 += sx[w][u * 16 + i + 1] * wreg[i + 1];
                }
                h[u] = fmaxf(a0 + a1, 0.f);
                g_h[(size_t)(v0 + u) * 32 + j] = h[u];
                seg[u] = g_didx[v0 + u];
            }
        }
        float m = h[0]; int cs = seg[0];
#pragma unroll
        for (int u = 1; u < 4; u++) {
            if (u < nv) {
                if (seg[u] == cs) m = fmaxf(m, h[u]);
                else {
                    atomicMax((int*)&g_ctx[cs * 32 + j], __float_as_int(m));
                    cs = seg[u]; m = h[u];
                }
            }
        }
        atomicMax((int*)&g_ctx[cs * 32 + j], __float_as_int(m));
        __syncwarp();
    }
}

// -------- per-segment: c2 = ctx @ W2[32:64] --------
__global__ void __launch_bounds__(256) k_ctx2(const float* __restrict__ W2, int N) {
    __shared__ float sW[32 * 32];
    __shared__ float sx[8][32];
    int tid = threadIdx.x;
    for (int i = tid; i < 32 * 32; i += 256) sW[i] = W2[32 * 32 + i];
    __syncthreads();
    int w = tid >> 5, j = tid & 31;
    int p = blockIdx.x * 8 + w;
    if (p >= N) return;
    sx[w][j] = g_ctx[p * 32 + j];
    __syncwarp();
    float a0 = 0.f, a1 = 0.f;
#pragma unroll
    for (int i = 0; i < 32; i += 2) {
        a0 += sx[w][i]     * sW[i * 32 + j];
        a1 += sx[w][i + 1] * sW[(i + 1) * 32 + j];
    }
    g_c2[p * 32 + j] = a0 + a1;
}

// ---------------- per-view comp (8 views/warp in 2 passes, split accumulators) ----------------
__global__ void __launch_bounds__(256) k_comp(const float* __restrict__ W2,
                                              const float* __restrict__ WK,
                                              const float* __restrict__ bK, int V) {
    __shared__ float sW[32 * 32];
    __shared__ float sWK[32 * 8];
    __shared__ __align__(16) float cat[8][132];
    __shared__ float kv[8][132];
    int tid = threadIdx.x;
    for (int i = tid; i < 32 * 32; i += 256) sW[i] = W2[i];
    for (int i = tid; i < 32 * 8;  i += 256) sWK[i] = WK[i];
    __syncthreads();
    int w = tid >> 5, j = tid & 31;
    int vbase = (blockIdx.x * 8 + w) * 8;

    for (int pass = 0; pass < 2; pass++) {
        int v0 = vbase + pass * 4;
        if (v0 >= V) break;
        int nv = V - v0; if (nv > 4) nv = 4;

        if (v0 + 3 < V) {
            float4 t = ((const float4*)(g_h + (size_t)v0 * 32))[j];
            float* d = &cat[w][j * 4];
            d[0] = t.x; d[1] = t.y; d[2] = t.z; d[3] = t.w;
        } else {
            for (int idx = j; idx < nv * 32; idx += 32)
                cat[w][idx] = g_h[(size_t)v0 * 32 + idx];
        }
        __syncwarp();

#pragma unroll
        for (int u = 0; u < 4; u++) {
            if (u < nv) {
                int sg = g_didx[v0 + u];
                float a0 = g_c2[sg * 32 + j], a1 = 0.f;
#pragma unroll
                for (int i = 0; i < 32; i += 2) {
                    a0 += cat[w][u * 32 + i]     * sW[i * 32 + j];
                    a1 += cat[w][u * 32 + i + 1] * sW[(i + 1) * 32 + j];
                }
                kv[w][u * 32 + j] = fmaxf(a0 + a1, 0.f);
            }
        }
        __syncwarp();

        int u = j >> 3, jq = j & 7;
        float c = 0.f;
        if (u < nv) {
            int segu = g_didx[v0 + u];
            float a0 = bK[jq], a1 = 0.f;
#pragma unroll
            for (int i = 0; i < 32; i += 2) {
                a0 += kv[w][u * 32 + i]     * sWK[i * 8 + jq];
                a1 += kv[w][u * 32 + i + 1] * sWK[(i + 1) * 8 + jq];
            }
            c = (a0 + a1) * g_q[(size_t)segu * 8 + jq];
        }
        c += __shfl_down_sync(0xffffffff, c, 4, 8);
        c += __shfl_down_sync(0xffffffff, c, 2, 8);
        c += __shfl_down_sync(0xffffffff, c, 1, 8);
        if (jq == 0 && u < nv) g_comp[v0 + u] = c * 0.35355339059327373f;
        __syncwarp();
    }
}

// ------- per-segment softmax + gate -> g_att (warp per segment, 8/block) -------
__global__ void __launch_bounds__(256) k_att(const int* __restrict__ csr,
                                             const float* __restrict__ gw,
                                             const float* __restrict__ gb,
                                             float* __restrict__ seen,
                                             int writeSeen, int N) {
    int w = threadIdx.x >> 5, lane = threadIdx.x & 31;
    int n = blockIdx.x * 8 + w;
    if (n >= N) return;
    int s = csr[n], e = csr[n + 1];
    if (e <= s) {
        if (writeSeen && lane == 0) seen[n] = 0.f;
        return;
    }
    float m = -INFINITY;
    for (int v = s + lane; v < e; v += 32) m = fmaxf(m, g_comp[v]);
#pragma unroll
    for (int off = 16; off > 0; off >>= 1)
        m = fmaxf(m, __shfl_xor_sync(0xffffffff, m, off));
    float sum = 0.f;
    for (int v = s + lane; v < e; v += 32) sum += expf(g_comp[v] - m);
#pragma unroll
    for (int off = 16; off > 0; off >>= 1)
        sum += __shfl_xor_sync(0xffffffff, sum, off);
    float gate = tanhf(fmaxf(gw[0] * m + gb[0], 0.f));
    float winv = gate / (sum + 1e-12f);
    for (int v = s + lane; v < e; v += 32)
        g_att[v] = expf(g_comp[v] - m) * winv;
    if (writeSeen && lane == 0) seen[n] = 1.f;
}

// ---------------- tensor-core GEMM machinery (split-bf16, 3-MMA, M=256) ----------------
__device__ __forceinline__ uint32_t sm_addr(const void* p) {
    return (uint32_t)__cvta_generic_to_shared(p);
}
__device__ __forceinline__ void ldsm4(uint32_t a, uint32_t* r) {
    asm volatile("ldmatrix.sync.aligned.m8n8.x4.shared.b16 {%0,%1,%2,%3}, [%4];"
                 : "=r"(r[0]), "=r"(r[1]), "=r"(r[2]), "=r"(r[3]) : "r"(a));
}
__device__ __forceinline__ void ldsm4t(uint32_t a, uint32_t* r) {
    asm volatile("ldmatrix.sync.aligned.m8n8.x4.trans.shared.b16 {%0,%1,%2,%3}, [%4];"
                 : "=r"(r[0]), "=r"(r[1]), "=r"(r[2]), "=r"(r[3]) : "r"(a));
}
__device__ __forceinline__ void mma16816(float* d, const uint32_t* a, uint32_t b0, uint32_t b1) {
    asm volatile("mma.sync.aligned.m16n8k16.row.col.f32.bf16.bf16.f32 "
                 "{%0,%1,%2,%3}, {%4,%5,%6,%7}, {%8,%9}, {%0,%1,%2,%3};"
                 : "+f"(d[0]), "+f"(d[1]), "+f"(d[2]), "+f"(d[3])
                 : "r"(a[0]), "r"(a[1]), "r"(a[2]), "r"(a[3]), "r"(b0), "r"(b1));
}
__device__ __forceinline__ void split4(float4 v, __nv_bfloat16* hi, __nv_bfloat16* lo) {
    float f[4] = {v.x, v.y, v.z, v.w};
    __nv_bfloat162 h01, h23, l01, l23;
    __nv_bfloat16 h0 = __float2bfloat16_rn(f[0]);
    __nv_bfloat16 h1 = __float2bfloat16_rn(f[1]);
    __nv_bfloat16 h2 = __float2bfloat16_rn(f[2]);
    __nv_bfloat16 h3 = __float2bfloat16_rn(f[3]);
    h01.x = h0; h01.y = h1; h23.x = h2; h23.y = h3;
    l01.x = __float2bfloat16_rn(f[0] - __bfloat162float(h0));
    l01.y = __float2bfloat16_rn(f[1] - __bfloat162float(h1));
    l23.x = __float2bfloat16_rn(f[2] - __bfloat162float(h2));
    l23.y = __float2bfloat16_rn(f[3] - __bfloat162float(h3));
    *reinterpret_cast<__nv_bfloat162*>(hi)     = h01;
    *reinterpret_cast<__nv_bfloat162*>(hi + 2) = h23;
    *reinterpret_cast<__nv_bfloat162*>(lo)     = l01;
    *reinterpret_cast<__nv_bfloat162*>(lo + 2) = l23;
}

__device__ __forceinline__ void gemm_loop(uint32_t aHi0, uint32_t aLo0,
                                          uint32_t bHi, uint32_t bLo,
                                          float (&acc)[2][16][4]) {
    const uint32_t CH = 16 * LDS * 2;
    uint32_t ah[2][2][4], al[2][2][4];
    ldsm4(aHi0,      ah[0][0]);
    ldsm4(aLo0,      al[0][0]);
    ldsm4(aHi0 + CH, ah[0][1]);
    ldsm4(aLo0 + CH, al[0][1]);
#pragma unroll
    for (int ks = 0; ks < 8; ks++) {
        const int cab = ks & 1, nab = cab ^ 1;
        if (ks < 7) {
            ldsm4(aHi0 + (ks + 1) * 32,      ah[nab][0]);
            ldsm4(aLo0 + (ks + 1) * 32,      al[nab][0]);
            ldsm4(aHi0 + CH + (ks + 1) * 32, ah[nab][1]);
            ldsm4(aLo0 + CH + (ks + 1) * 32, al[nab][1]);
        }
        uint32_t bBaseH = bHi + (uint32_t)(ks * 16 * LDS) * 2u;
        uint32_t bBaseL = bLo + (uint32_t)(ks * 16 * LDS) * 2u;
        uint32_t bh[2][4], bl[2][4];
        ldsm4t(bBaseH, bh[0]);
        ldsm4t(bBaseL, bl[0]);
#pragma unroll
        for (int np = 0; np < 8; np++) {
            const int cur = np & 1, nxt = cur ^ 1;
            if (np < 7) {
                ldsm4t(bBaseH + (np + 1) * 32, bh[nxt]);
                ldsm4t(bBaseL + (np + 1) * 32, bl[nxt]);
            }
#pragma unroll
            for (int c = 0; c < 2; c++) {
                mma16816(acc[c][np * 2],     ah[cab][c], bh[cur][0], bh[cur][1]);
                mma16816(acc[c][np * 2 + 1], ah[cab][c], bh[cur][2], bh[cur][3]);
                mma16816(acc[c][np * 2],     ah[cab][c], bl[cur][0], bl[cur][1]);
                mma16816(acc[c][np * 2 + 1], ah[cab][c], bl[cur][2], bl[cur][3]);
                mma16816(acc[c][np * 2],     al[cab][c], bh[cur][0], bh[cur][1]);
                mma16816(acc[c][np * 2 + 1], al[cab][c], bh[cur][2], bh[cur][3]);
            }
        }
    }
}

#define MT 256
#define AB_BYTES ((2 * MT + 2 * 128) * LDS * 2)
#define G1_SMEM (AB_BYTES + 256 * 4 + 256 * 4)

// pool1[seg] += att[v] * relu(X[v]@W1)
__global__ void __launch_bounds__(256, 1) k_gemm1(const float* __restrict__ X,
                                                  const float* __restrict__ W1,
                                                  int V) {
    extern __shared__ unsigned char smraw[];
    __nv_bfloat16* sAhi = (__nv_bfloat16*)smraw;
    __nv_bfloat16* sAlo = sAhi + (size_t)MT * LDS;
    __nv_bfloat16* sBhi = sAhi + (size_t)2 * MT * LDS;
    __nv_bfloat16* sBlo = sBhi + (size_t)128 * LDS;
    float* satt = (float*)(smraw + AB_BYTES);
    int*   sdid = (int*)(smraw + AB_BYTES + 256 * 4);
    float* smemF = (float*)smraw;     // epilogue alias

    int tid = threadIdx.x;
    int m0 = blockIdx.x * MT;

    {
        long gm = m0 + tid;
        bool ok = gm < V;
        satt[tid] = ok ? g_att[gm] : 0.f;
        sdid[tid] = g_didx[ok ? gm : (V - 1)];
    }

    for (int idx = tid; idx < MT * 32; idx += 256) {
        int r = idx >> 5, c4 = idx & 31;
        float4 v = (m0 + r < V) ? ((const float4*)X)[(size_t)(m0 + r) * 32 + c4]
                                : make_float4(0.f, 0.f, 0.f, 0.f);
        split4(v, sAhi + r * LDS + c4 * 4, sAlo + r * LDS + c4 * 4);
    }
    for (int idx = tid; idx < 128 * 32; idx += 256) {
        int r = idx >> 5, c4 = idx & 31;
        float4 v = ((const float4*)W1)[idx];
        split4(v, sBhi + r * LDS + c4 * 4, sBlo + r * LDS + c4 * 4);
    }
    __syncthreads();

    int w = tid >> 5, lane = tid & 31;
    int lr = lane & 15, lc = (lane >> 4) * 8;
    uint32_t aHi = sm_addr(sAhi + (w * 32 + lr) * LDS + lc);
    uint32_t aLo = sm_addr(sAlo + (w * 32 + lr) * LDS + lc);
    uint32_t bHi = sm_addr(sBhi + lr * LDS + lc);
    uint32_t bLo = sm_addr(sBlo + lr * LDS + lc);

    float acc[2][16][4];
#pragma unroll
    for (int c = 0; c < 2; c++)
#pragma unroll
        for (int t = 0; t < 16; t++)
#pragma unroll
            for (int i = 0; i < 4; i++) acc[c][t][i] = 0.f;

    gemm_loop(aHi, aLo, bHi, bLo, acc);
    __syncthreads();   // safe to alias smemF

    int grp = lane >> 2, tq = lane & 3;
#pragma unroll
    for (int c = 0; c < 2; c++)
#pragma unroll
    for (int t = 0; t < 16; t++) {
        int col = t * 8 + tq * 2;
        int r0 = w * 32 + c * 16 + grp, r1 = r0 + 8;
        float a0 = satt[r0], a1 = satt[r1];
        smemF[r0 * 132 + col]     = fmaxf(acc[c][t][0], 0.f) * a0;
        smemF[r0 * 132 + col + 1] = fmaxf(acc[c][t][1], 0.f) * a0;
        smemF[r1 * 132 + col]     = fmaxf(acc[c][t][2], 0.f) * a1;
        smemF[r1 * 132 + col + 1] = fmaxf(acc[c][t][3], 0.f) * a1;
    }
    __syncthreads();

    // segmented reduction: 4 independent 32-row runs per thread (chain /4)
    {
        int half = tid >> 7, ch = tid & 127;
        int base = half * 128;
        float run[4];
        int cur[4];
#pragma unroll
        for (int q = 0; q < 4; q++) {
            int row = base + q * 32;
            run[q] = smemF[row * 132 + ch];
            cur[q] = sdid[row];
        }
        for (int r = 1; r < 32; r++) {
#pragma unroll
            for (int q = 0; q < 4; q++) {
                int row = base + q * 32 + r;
                int sg = sdid[row];
                float v = smemF[row * 132 + ch];
                if (sg == cur[q]) run[q] += v;
                else {
                    atomicAdd(&g_pool1[(size_t)cur[q] * 128 + ch], run[q]);
                    cur[q] = sg; run[q] = v;
                }
            }
        }
#pragma unroll
        for (int q = 0; q < 4; q++)
            atomicAdd(&g_pool1[(size_t)cur[q] * 128 + ch], run[q]);
    }
}

#define G2_SMEM AB_BYTES

// out[N,128] = pool1[N,128] @ W2
__global__ void __launch_bounds__(256, 1) k_gemm2(const float* __restrict__ W2,
                                                  float* __restrict__ out, int N) {
    extern __shared__ __nv_bfloat16 sm[];
    __nv_bfloat16* sAhi = sm;
    __nv_bfloat16* sAlo = sm + (size_t)MT * LDS;
    __nv_bfloat16* sBhi = sm + (size_t)2 * MT * LDS;
    __nv_bfloat16* sBlo = sBhi + (size_t)128 * LDS;

    int tid = threadIdx.x;
    int m0 = blockIdx.x * MT;

    for (int idx = tid; idx < MT * 32; idx += 256) {
        int r = idx >> 5, c4 = idx & 31;
        float4 v = (m0 + r < N) ? ((const float4*)g_pool1)[(size_t)(m0 + r) * 32 + c4]
                                : make_float4(0.f, 0.f, 0.f, 0.f);
        split4(v, sAhi + r * LDS + c4 * 4, sAlo + r * LDS + c4 * 4);
    }
    for (int idx = tid; idx < 128 * 32; idx += 256) {
        int r = idx >> 5, c4 = idx & 31;
        float4 v = ((const float4*)W2)[idx];
        split4(v, sBhi + r * LDS + c4 * 4, sBlo + r * LDS + c4 * 4);
    }
    __syncthreads();

    int w = tid >> 5, lane = tid & 31;
    int lr = lane & 15, lc = (lane >> 4) * 8;
    uint32_t aHi = sm_addr(sAhi + (w * 32 + lr) * LDS + lc);
    uint32_t aLo = sm_addr(sAlo + (w * 32 + lr) * LDS + lc);
    uint32_t bHi = sm_addr(sBhi + lr * LDS + lc);
    uint32_t bLo = sm_addr(sBlo + lr * LDS + lc);

    float acc[2][16][4];
#pragma unroll
    for (int c = 0; c < 2; c++)
#pragma unroll
        for (int t = 0; t < 16; t++)
#pragma unroll
            for (int i = 0; i < 4; i++) acc[c][t][i] = 0.f;

    gemm_loop(aHi, aLo, bHi, bLo, acc);

    int grp = lane >> 2, tq = lane & 3;
#pragma unroll
    for (int c = 0; c < 2; c++)
#pragma unroll
    for (int t = 0; t < 16; t++) {
        int col = t * 8 + tq * 2;
        int gm0 = m0 + w * 32 + c * 16 + grp;
        int gm1 = gm0 + 8;
        if (gm0 < N) {
            float2 o; o.x = acc[c][t][0]; o.y = acc[c][t][1];
            *reinterpret_cast<float2*>(&out[(size_t)gm0 * 128 + col]) = o;
        }
        if (gm1 < N) {
            float2 o; o.x = acc[c][t][2]; o.y = acc[c][t][3];
            *reinterpret_cast<float2*>(&out[(size_t)gm1 * 128 + col]) = o;
        }
    }
}

// ---------------- launch ----------------
extern "C" void kernel_launch(void* const* d_in, const int* in_sizes, int n_in,
                              void* d_out, int out_size) {
    const float* x_main  = (const float*)d_in[0];
    const float* x_mod   = (const float*)d_in[1];
    const float* x_map   = (const float*)d_in[2];
    const int*   csr     = (const int*)  d_in[3];
    const float* W_main1 = (const float*)d_in[4];
    const float* W_main2 = (const float*)d_in[5];
    const float* W_map1  = (const float*)d_in[6];
    const float* W_map2  = (const float*)d_in[7];
    const float* W_mod1  = (const float*)d_in[8];
    const float* W_mod2  = (const float*)d_in[9];
    const float* WQ      = (const float*)d_in[10];
    const float* bQ      = (const float*)d_in[11];
    const float* WK      = (const float*)d_in[12];
    const float* bK      = (const float*)d_in[13];
    const float* gw      = (const float*)d_in[14];
    const float* gb      = (const float*)d_in[15];

    int N = in_sizes[3] - 1;
    int V = in_sizes[2] / 16;

    float* out = (float*)d_out;
    float* seen = nullptr;
    int writeSeen = 0;
    long long written = (long long)N * 128;
    if ((long long)out_size >= (long long)N * 128 + N) {
        seen = out + (size_t)N * 128;
        writeSeen = 1;
        written += N;
    }

    k_zero_scratch<<<(N * 160 + 255) / 256, 256>>>(N * 32, N * 128);
    k_didx<<<(V + 255) / 256, 256>>>(csr, N, V);
    k_q<<<(N + 31) / 32, 256>>>(x_main, W_main1, W_main2, WQ, bQ, N);
    k_h<<<(V + 63) / 64, 256>>>(x_map, W_map1, V);
    k_ctx2<<<(N + 7) / 8, 256>>>(W_map2, N);
    k_comp<<<(V + 63) / 64, 256>>>(W_map2, WK, bK, V);
    k_att<<<(N + 7) / 8, 256>>>(csr, gw, gb, seen, writeSeen, N);

    cudaFuncSetAttribute(k_gemm1, cudaFuncAttributeMaxDynamicSharedMemorySize, G1_SMEM);
    k_gemm1<<<(V + MT - 1) / MT, 256, G1_SMEM>>>(x_mod, W_mod1, V);

    cudaFuncSetAttribute(k_gemm2, cudaFuncAttributeMaxDynamicSharedMemorySize, G2_SMEM);
    k_gemm2<<<(N + MT - 1) / MT, 256, G2_SMEM>>>(W_mod2, out, N);

    long long tail = (long long)out_size - written;
    if (tail > 0) {
        k_tail_zero<<<(int)((tail + 255) / 256), 256>>>(out + written, (int)tail);
    }
}